// round 12
// baseline (speedup 1.0000x reference)
#include <cuda_runtime.h>

namespace qc {

constexpr int NQ = 14;
constexpr int NL = 4;
constexpr int NS = 1 << NQ;       // 16384 amplitudes
constexpr int NT = 512;           // one 32-amp window per thread, all gates in-thread
constexpr int NC = NQ - 1;
constexpr int NWARP = NT / 32;    // 16
constexpr int NGL = NL - 1;       // gate layers stored (layers 1..3)

// shared memory layout (float offsets). State float2[NS].
constexpr int OFF_U   = 2 * NS;                    // 42 gates * 8 floats
constexpr int OFF_V   = OFF_U + NGL * NQ * 8;      // 14 qubits * 2 cplx
constexpr int OFF_RED = OFF_V + NQ * 4;
constexpr int SMEM_FLOATS = OFF_RED + NWARP * NQ;
constexpr int SMEM_BYTES  = SMEM_FLOATS * 4;

// XOR swizzle on float2 index: conflict-free for S in {0,5,9} (verified:
// per-o-step warp addresses have low bits = lane ^ const).
__device__ __forceinline__ int swz(int i) { return i ^ ((i >> 5) & 31); }

__device__ __forceinline__ float2 cmul(float2 a, float2 b) {
  return make_float2(a.x * b.x - a.y * b.y, a.x * b.y + a.y * b.x);
}

// 5-bit prefix-xor relabel: the in-window CNOT chain c(S..S+3 -> S+1..S+4)
__host__ __device__ constexpr int pxm5(int o) {
  return (o ^ (o << 1) ^ (o << 2) ^ (o << 3) ^ (o << 4)) & 31;
}

template<int S>
__device__ __forceinline__ int wbase(int g) {
  return ((g >> S) << (S + 5)) | (g & ((1 << S) - 1));
}

template<int S>
__device__ __forceinline__ void load32(const float2* __restrict__ st, int g,
                                       float* vr, float* vi) {
  const int base = wbase<S>(g);
#pragma unroll
  for (int o = 0; o < 32; ++o) {
    const float2 v = st[swz(base | (o << S))];
    vr[o] = v.x; vi[o] = v.y;
  }
}

// store; PX: relabel o->pxm5(o) (folds chain c(S+0..S+3)); cbmask (0 or 31)
// folds a control-outside c(S-1): XOR on the LABEL (lesson from r9).
template<int S, bool PX>
__device__ __forceinline__ void store32(float2* __restrict__ st, int g,
                                        const float* vr, const float* vi, int cbmask) {
  const int base = wbase<S>(g);
#pragma unroll
  for (int o = 0; o < 32; ++o) {
    const int m = (PX ? pxm5(o) : o) ^ cbmask;
    st[swz(base | (m << S))] = make_float2(vr[o], vi[o]);
  }
}

// in-thread 1q gate butterfly on local bit J (32-amp window)
template<int J>
__device__ __forceinline__ void gateBit5(float* vr, float* vi, const float* __restrict__ u) {
  const float u0 = u[0], u1 = u[1], u2 = u[2], u3 = u[3];
  const float u4 = u[4], u5 = u[5], u6 = u[6], u7 = u[7];
#pragma unroll
  for (int o = 0; o < 32; ++o) {
    if (o & (1 << J)) continue;
    const int o1 = o | (1 << J);
    const float ar = vr[o], ai = vi[o], br = vr[o1], bi = vi[o1];
    vr[o]  = u0*ar - u1*ai + u2*br - u3*bi;
    vi[o]  = u0*ai + u1*ar + u2*bi + u3*br;
    vr[o1] = u4*ar - u5*ai + u6*br - u7*bi;
    vi[o1] = u4*ai + u5*ar + u6*bi + u7*br;
  }
}

// register-level chain relabel (free: pure renaming)
__device__ __forceinline__ void relabel5(const float* vr, const float* vi,
                                         float* wr, float* wi) {
#pragma unroll
  for (int o = 0; o < 32; ++o) { wr[pxm5(o)] = vr[o]; wi[pxm5(o)] = vi[o]; }
}

__global__ void __launch_bounds__(NT, 1)
qc_kernel(const float* __restrict__ x, const float* __restrict__ prx,
          const float* __restrict__ pry, const float* __restrict__ prz,
          const float* __restrict__ pent, float* __restrict__ out) {
  extern __shared__ float sm[];
  float2* st = reinterpret_cast<float2*>(sm);
  float2* vv = reinterpret_cast<float2*>(sm + OFF_V);
  const int tid = threadIdx.x;
  const int g   = tid;              // window id (9 bits)
  const int b   = blockIdx.x;

  // ---- prologue: gates for layers 1..3 (U' = Rz*Ry*Rx * RZ_ent[l-1]) ----
  if (tid < NGL * NQ) {
    const int q = tid % NQ;
    const int idx = tid + NQ;       // (l,q), l = tid/NQ + 1
    float cx, sx, cy, sy, cz, sz;
    sincosf(0.5f * prx[idx], &sx, &cx);
    sincosf(0.5f * pry[idx], &sy, &cy);
    sincosf(0.5f * prz[idx], &sz, &cz);
    const float r00x =  cy*cx, r00y =  sy*sx;
    const float r01x = -sy*cx, r01y = -cy*sx;
    const float r10x =  sy*cx, r10y = -cy*sx;
    const float r11x =  cy*cx, r11y = -sy*sx;
    float u0 = r00x*cz + r00y*sz, u1 = r00y*cz - r00x*sz;
    float u2 = r01x*cz + r01y*sz, u3 = r01y*cz - r01x*sz;
    float u4 = r10x*cz - r10y*sz, u5 = r10x*sz + r10y*cz;
    float u6 = r11x*cz - r11y*sz, u7 = r11x*sz + r11y*cz;
    if (q >= 1) {
      float c, s; sincosf(0.5f * pent[(tid / NQ) * NC + (q - 1)], &s, &c);
      float a;
      a = u0*c + u1*s;  u1 = u1*c - u0*s;  u0 = a;   // col 0 *= e^{-i t/2}
      a = u4*c + u5*s;  u5 = u5*c - u4*s;  u4 = a;
      a = u2*c - u3*s;  u3 = u3*c + u2*s;  u2 = a;   // col 1 *= e^{+i t/2}
      a = u6*c - u7*s;  u7 = u7*c + u6*s;  u6 = a;
    }
    float* u = sm + OFF_U + tid * 8;
    u[0] = u0; u[1] = u1; u[2] = u2; u[3] = u3;
    u[4] = u4; u[5] = u5; u[6] = u6; u[7] = u7;
  }
  // ---- layer-0 gates folded into product vectors: v_j = U_0(j)*(c_j,s_j)^T ----
  if (tid >= 64 && tid < 64 + NQ) {
    const int j = tid - 64;
    float cx, sx, cy, sy, cz, sz;
    sincosf(0.5f * prx[j], &sx, &cx);
    sincosf(0.5f * pry[j], &sy, &cy);
    sincosf(0.5f * prz[j], &sz, &cz);
    const float r00x =  cy*cx, r00y =  sy*sx;
    const float r01x = -sy*cx, r01y = -cy*sx;
    const float r10x =  sy*cx, r10y = -cy*sx;
    const float r11x =  cy*cx, r11y = -sy*sx;
    const float u0 = r00x*cz + r00y*sz, u1 = r00y*cz - r00x*sz;
    const float u2 = r01x*cz + r01y*sz, u3 = r01y*cz - r01x*sz;
    const float u4 = r10x*cz - r10y*sz, u5 = r10x*sz + r10y*cz;
    const float u6 = r11x*cz - r11y*sz, u7 = r11x*sz + r11y*cz;
    const float th = 0.5f * 3.14159265358979323846f * tanhf(x[b * NQ + j]);
    float c, s; sincosf(th, &s, &c);
    vv[j * 2 + 0] = make_float2(u0 * c + u2 * s, u1 * c + u3 * s);
    vv[j * 2 + 1] = make_float2(u4 * c + u6 * s, u5 * c + u7 * s);
  }
  __syncthreads();

  const float* ul1 = sm + OFF_U;
  const float* ul2 = sm + OFF_U + 14 * 8;
  const float* ul3 = sm + OFF_U + 28 * 8;
  const int cb = (g >> 4) & 1;           // qubit-4 value for S=5 windows
  const int cbm = cb ? 31 : 0;           // c4 fold: label XOR (px5 of e0)
  float vr[32], vi[32];

  // ===== P1: synth + G1(0-4) + C1(0-3)  [S=0] =====
  {
    // amp(y) = prod v_j[x_j], x_j = y_j^y_{j-1}; y = (g<<5)|o  (r7 synth, proven)
    const int t = g;
    float2 P = vv[6 * 2 + (((t >> 1) ^ t) & 1)];           // x6 = t1^t0
#pragma unroll
    for (int j = 7; j < NQ; ++j)
      P = cmul(P, vv[j * 2 + (((t >> (j - 5)) ^ (t >> (j - 6))) & 1)]);
    const int t0 = t & 1;
    float2 Pv5[2];                                          // x5 = t0 ^ o4
    Pv5[0] = cmul(P, vv[5 * 2 + t0]);
    Pv5[1] = cmul(P, vv[5 * 2 + (t0 ^ 1)]);
    float2 a34[4];                                          // [o3 + 2*o4]
#pragma unroll
    for (int o3 = 0; o3 < 2; ++o3)
#pragma unroll
      for (int o4 = 0; o4 < 2; ++o4)
        a34[o3 + 2 * o4] = cmul(vv[4 * 2 + (o4 ^ o3)], Pv5[o4]);
    float2 w2[8];                                           // [o2 + 2*o3 + 4*o4]
#pragma unroll
    for (int o2 = 0; o2 < 2; ++o2)
#pragma unroll
      for (int o3 = 0; o3 < 2; ++o3)
#pragma unroll
        for (int o4 = 0; o4 < 2; ++o4)
          w2[o2 + 2 * o3 + 4 * o4] = cmul(vv[3 * 2 + (o3 ^ o2)], a34[o3 + 2 * o4]);
    float2 g8[8];                                           // [o0 + 2*o1 + 4*o2]
#pragma unroll
    for (int o0 = 0; o0 < 2; ++o0)
#pragma unroll
      for (int o1 = 0; o1 < 2; ++o1) {
        const float2 h = cmul(vv[0 * 2 + o0], vv[1 * 2 + (o1 ^ o0)]);
#pragma unroll
        for (int o2 = 0; o2 < 2; ++o2)
          g8[o0 + 2 * o1 + 4 * o2] = cmul(h, vv[2 * 2 + (o2 ^ o1)]);
      }
#pragma unroll
    for (int o = 0; o < 32; ++o) {
      const float2 a = cmul(g8[o & 7], w2[(o >> 2) & 7]);
      vr[o] = a.x; vi[o] = a.y;
    }
    gateBit5<0>(vr, vi, ul1 + 0 * 8);
    gateBit5<1>(vr, vi, ul1 + 1 * 8);
    gateBit5<2>(vr, vi, ul1 + 2 * 8);
    gateBit5<3>(vr, vi, ul1 + 3 * 8);
    gateBit5<4>(vr, vi, ul1 + 4 * 8);
    store32<0, true>(st, g, vr, vi, 0);       // c0-c3 via px relabel
  }
  __syncwarp();   // P1->P2 dependency is warp-local (P2 reads its own warp's windows)

  // ===== P2: G1(5-9) + C1(4-8)  [S=5] =====
  {
    load32<5>(st, g, vr, vi);
    gateBit5<0>(vr, vi, ul1 + 5 * 8);
    gateBit5<1>(vr, vi, ul1 + 6 * 8);
    gateBit5<2>(vr, vi, ul1 + 7 * 8);
    gateBit5<3>(vr, vi, ul1 + 8 * 8);
    gateBit5<4>(vr, vi, ul1 + 9 * 8);
    store32<5, true>(st, g, vr, vi, cbm);     // c4 (ctrl outside) + c5-c8 folded
  }
  __syncthreads();

  // ===== P3: G1(10-13) + C1(9-12) + G2(9-13)  [S=9] =====
  {
    load32<9>(st, g, vr, vi);
    gateBit5<1>(vr, vi, ul1 + 10 * 8);
    gateBit5<2>(vr, vi, ul1 + 11 * 8);
    gateBit5<3>(vr, vi, ul1 + 12 * 8);
    gateBit5<4>(vr, vi, ul1 + 13 * 8);
    float wr[32], wi[32];
    relabel5(vr, vi, wr, wi);                 // c9-c12 (ctrl qubit 9 in-window)
    gateBit5<0>(wr, wi, ul2 + 9 * 8);
    gateBit5<1>(wr, wi, ul2 + 10 * 8);
    gateBit5<2>(wr, wi, ul2 + 11 * 8);
    gateBit5<3>(wr, wi, ul2 + 12 * 8);
    gateBit5<4>(wr, wi, ul2 + 13 * 8);
    store32<9, false>(st, g, wr, wi, 0);
  }
  __syncthreads();

  // ===== P4: G2(0-4) + C2(0-3)  [S=0] =====
  {
    load32<0>(st, g, vr, vi);
    gateBit5<0>(vr, vi, ul2 + 0 * 8);
    gateBit5<1>(vr, vi, ul2 + 1 * 8);
    gateBit5<2>(vr, vi, ul2 + 2 * 8);
    gateBit5<3>(vr, vi, ul2 + 3 * 8);
    gateBit5<4>(vr, vi, ul2 + 4 * 8);
    store32<0, true>(st, g, vr, vi, 0);
  }
  __syncwarp();

  // ===== P5: G2(5-8) + C2(4-8)  [S=5] =====
  {
    load32<5>(st, g, vr, vi);
    gateBit5<0>(vr, vi, ul2 + 5 * 8);
    gateBit5<1>(vr, vi, ul2 + 6 * 8);
    gateBit5<2>(vr, vi, ul2 + 7 * 8);
    gateBit5<3>(vr, vi, ul2 + 8 * 8);
    // G2(9) already applied in P3
    store32<5, true>(st, g, vr, vi, cbm);
  }
  __syncthreads();

  // ===== P6: C2(9-12) + G3(9-13)  [S=9] =====
  {
    load32<9>(st, g, vr, vi);
    float wr[32], wi[32];
    relabel5(vr, vi, wr, wi);
    gateBit5<0>(wr, wi, ul3 + 9 * 8);
    gateBit5<1>(wr, wi, ul3 + 10 * 8);
    gateBit5<2>(wr, wi, ul3 + 11 * 8);
    gateBit5<3>(wr, wi, ul3 + 12 * 8);
    gateBit5<4>(wr, wi, ul3 + 13 * 8);
    store32<9, false>(st, g, wr, wi, 0);
  }
  __syncthreads();

  // ===== P7: G3(0-4) + C3(0-3)  [S=0] =====
  {
    load32<0>(st, g, vr, vi);
    gateBit5<0>(vr, vi, ul3 + 0 * 8);
    gateBit5<1>(vr, vi, ul3 + 1 * 8);
    gateBit5<2>(vr, vi, ul3 + 2 * 8);
    gateBit5<3>(vr, vi, ul3 + 3 * 8);
    gateBit5<4>(vr, vi, ul3 + 4 * 8);
    store32<0, true>(st, g, vr, vi, 0);
  }
  __syncwarp();

  // ===== P8: G3(5-8) + C3(4-8)  [S=5] =====
  {
    load32<5>(st, g, vr, vi);
    gateBit5<0>(vr, vi, ul3 + 5 * 8);
    gateBit5<1>(vr, vi, ul3 + 6 * 8);
    gateBit5<2>(vr, vi, ul3 + 7 * 8);
    gateBit5<3>(vr, vi, ul3 + 8 * 8);
    store32<5, true>(st, g, vr, vi, cbm);
  }
  __syncthreads();

  // ===== P9: C3(9-12) + MEAS  [S=9] =====
  float acc[NQ];
  {
    load32<9>(st, g, vr, vi);
    float tot = 0.0f, s0 = 0.0f, s1 = 0.0f, s2 = 0.0f, s3 = 0.0f, s4 = 0.0f;
#pragma unroll
    for (int o = 0; o < 32; ++o) {
      const float pr = vr[o] * vr[o] + vi[o] * vi[o];
      const int m = pxm5(o);               // labels after c9-c12 (no data movement)
      tot += pr;
      if (m & 1)  s0 += pr;
      if (m & 2)  s1 += pr;
      if (m & 4)  s2 += pr;
      if (m & 8)  s3 += pr;
      if (m & 16) s4 += pr;
    }
    acc[9]  = tot - 2.0f * s0;
    acc[10] = tot - 2.0f * s1;
    acc[11] = tot - 2.0f * s2;
    acc[12] = tot - 2.0f * s3;
    acc[13] = tot - 2.0f * s4;
#pragma unroll
    for (int q = 0; q < 9; ++q)
      acc[q] = ((g >> q) & 1) ? -tot : tot;
  }

  // ---- reduction ----
#pragma unroll
  for (int q = 0; q < NQ; ++q)
#pragma unroll
    for (int off = 16; off > 0; off >>= 1)
      acc[q] += __shfl_xor_sync(0xffffffffu, acc[q], off);
  const int warp = tid >> 5;
  __syncthreads();
  if ((tid & 31) == 0) {
#pragma unroll
    for (int q = 0; q < NQ; ++q) sm[OFF_RED + warp * NQ + q] = acc[q];
  }
  __syncthreads();
  if (tid < NQ) {
    float s = 0.0f;
#pragma unroll
    for (int w = 0; w < NWARP; ++w) s += sm[OFF_RED + w * NQ + tid];
    out[b * NQ + tid] = s;
  }
}

} // namespace qc

extern "C" void kernel_launch(void* const* d_in, const int* in_sizes, int n_in,
                              void* d_out, int out_size) {
  const float* x    = (const float*)d_in[0];
  const float* prx  = (const float*)d_in[1];
  const float* pry  = (const float*)d_in[2];
  const float* prz  = (const float*)d_in[3];
  const float* pent = (const float*)d_in[4];
  float* out = (float*)d_out;
  const int batch = in_sizes[0] / qc::NQ;   // 128
  cudaFuncSetAttribute(qc::qc_kernel, cudaFuncAttributeMaxDynamicSharedMemorySize,
                       qc::SMEM_BYTES);
  qc::qc_kernel<<<batch, qc::NT, qc::SMEM_BYTES>>>(x, prx, pry, prz, pent, out);
}

// round 14
// speedup vs baseline: 1.2575x; 1.2575x over previous
#include <cuda_runtime.h>

namespace qc {

constexpr int NQ = 14;
constexpr int NL = 4;
constexpr int NS = 1 << NQ;       // 16384 amplitudes
constexpr int NT = 512;           // one 32-amp window per thread
constexpr int NC = NQ - 1;
constexpr int NWARP = NT / 32;    // 16
constexpr int NGATE = 42;         // layers 1..3 x 14 qubits

// shared layout (float offsets). State float2[NS].
constexpr int OFF_Z   = 2 * NS;                  // 42 gates * 6 floats: cb2 sb2 cg sg ca sa
constexpr int OFF_V   = OFF_Z + NGATE * 6;       // 14 qubits * 2 cplx product vectors
constexpr int OFF_LUT = OFF_V + NQ * 4;          // 14 LUTs * 32 float2
constexpr int OFF_RED = OFF_LUT + 14 * 64;
constexpr int SMEM_FLOATS = OFF_RED + NWARP * NQ;
constexpr int SMEM_BYTES  = SMEM_FLOATS * 4;

// LUT ids
enum { L0 = 0, L1, L2a, L2b, L3a, L3b, L3c, L4a, L4b, L5a, L5b, L6, L7, L8 };

__device__ __forceinline__ int swz(int i) { return i ^ ((i >> 5) & 31); }

__device__ __forceinline__ float2 cmul(float2 a, float2 b) {
  return make_float2(a.x * b.x - a.y * b.y, a.x * b.y + a.y * b.x);
}

// 5-bit prefix-xor relabel (in-window CNOT chain)
__host__ __device__ constexpr int pxm5(int o) {
  return (o ^ (o << 1) ^ (o << 2) ^ (o << 3) ^ (o << 4)) & 31;
}

template<int S>
__device__ __forceinline__ int wbase(int g) {
  return ((g >> S) << (S + 5)) | (g & ((1 << S) - 1));
}

template<int S>
__device__ __forceinline__ void load32(const float2* __restrict__ st, int g,
                                       float* vr, float* vi) {
  const int base = wbase<S>(g);
#pragma unroll
  for (int o = 0; o < 32; ++o) {
    const float2 v = st[swz(base | (o << S))];
    vr[o] = v.x; vi[o] = v.y;
  }
}

template<int S, bool PX>
__device__ __forceinline__ void store32(float2* __restrict__ st, int g,
                                        const float* vr, const float* vi, int cbmask) {
  const int base = wbase<S>(g);
#pragma unroll
  for (int o = 0; o < 32; ++o) {
    const int m = (PX ? pxm5(o) : o) ^ cbmask;
    st[swz(base | (m << S))] = make_float2(vr[o], vi[o]);
  }
}

// REAL Ry butterfly on local bit J: 8 FFMA/pair (vs 16 complex)
template<int J>
__device__ __forceinline__ void ryBit5(float* vr, float* vi, const float* __restrict__ z) {
  const float c = z[0], s = z[1];
#pragma unroll
  for (int o = 0; o < 32; ++o) {
    if (o & (1 << J)) continue;
    const int o1 = o | (1 << J);
    const float ar = vr[o], ai = vi[o], br = vr[o1], bi = vi[o1];
    vr[o]  = c*ar - s*br;   vi[o]  = c*ai - s*bi;
    vr[o1] = s*ar + c*br;   vi[o1] = s*ai + c*bi;
  }
}

// apply a 32-entry complex diagonal LUT (broadcast LDS + 4 FFMA per amp)
__device__ __forceinline__ void applyLUT(float* vr, float* vi, const float2* __restrict__ lut) {
#pragma unroll
  for (int o = 0; o < 32; ++o) {
    const float2 w = lut[o];
    const float r = vr[o] * w.x - vi[o] * w.y;
    vi[o] = vr[o] * w.y + vi[o] * w.x;
    vr[o] = r;
  }
}

__device__ __forceinline__ void relabel5(const float* vr, const float* vi,
                                         float* wr, float* wi) {
#pragma unroll
  for (int o = 0; o < 32; ++o) { wr[pxm5(o)] = vr[o]; wi[pxm5(o)] = vi[o]; }
}

__global__ void __launch_bounds__(NT, 1)
qc_kernel(const float* __restrict__ x, const float* __restrict__ prx,
          const float* __restrict__ pry, const float* __restrict__ prz,
          const float* __restrict__ pent, float* __restrict__ out) {
  extern __shared__ float sm[];
  float2* st = reinterpret_cast<float2*>(sm);
  float2* vv = reinterpret_cast<float2*>(sm + OFF_V);
  float2* lutbase = reinterpret_cast<float2*>(sm + OFF_LUT);
  const int tid = threadIdx.x;
  const int g   = tid;
  const int b   = blockIdx.x;

  // ===== stage A: per-gate ZYZ (layers 1..3, ent-RZ merged) + layer-0 vectors =====
  if (tid < NGATE) {
    const int q = tid % NQ;
    const int idx = tid + NQ;     // (l,q), l = tid/NQ + 1
    float cx, sx, cy, sy, cz, sz;
    sincosf(0.5f * prx[idx], &sx, &cx);
    sincosf(0.5f * pry[idx], &sy, &cy);
    sincosf(0.5f * prz[idx], &sz, &cz);
    const float r00x =  cy*cx, r00y =  sy*sx;
    const float r01x = -sy*cx, r01y = -cy*sx;
    const float r10x =  sy*cx, r10y = -cy*sx;
    const float r11x =  cy*cx, r11y = -sy*sx;
    float u0 = r00x*cz + r00y*sz, u1 = r00y*cz - r00x*sz;
    float u2 = r01x*cz + r01y*sz, u3 = r01y*cz - r01x*sz;
    float u4 = r10x*cz - r10y*sz, u5 = r10x*sz + r10y*cz;
    if (q >= 1) {
      float c, s; sincosf(0.5f * pent[(tid / NQ) * NC + (q - 1)], &s, &c);
      float a;
      a = u0*c + u1*s;  u1 = u1*c - u0*s;  u0 = a;   // col 0 *= e^{-i t/2}
      a = u4*c + u5*s;  u5 = u5*c - u4*s;  u4 = a;
      a = u2*c - u3*s;  u3 = u3*c + u2*s;  u2 = a;   // col 1 *= e^{+i t/2}
    }
    // ZYZ: U = Rz(gam)*Ry(bet)*Rz(alp);  U is SU(2)
    const float cb2 = sqrtf(u0*u0 + u1*u1);     // cos(bet/2)
    const float sb2 = sqrtf(u4*u4 + u5*u5);     // sin(bet/2)
    const float php = -atan2f(u1, u0);          // (gam+alp)/2
    const float phm =  atan2f(u5, u4);          // (gam-alp)/2
    float sg, cg, sa, ca;
    sincosf(0.5f * (php + phm), &sg, &cg);      // gam/2
    sincosf(0.5f * (php - phm), &sa, &ca);      // alp/2
    float* z = sm + OFF_Z + tid * 6;
    z[0] = cb2; z[1] = sb2; z[2] = cg; z[3] = sg; z[4] = ca; z[5] = sa;
  }
  if (tid >= 64 && tid < 64 + NQ) {
    const int j = tid - 64;
    float cx, sx, cy, sy, cz, sz;
    sincosf(0.5f * prx[j], &sx, &cx);
    sincosf(0.5f * pry[j], &sy, &cy);
    sincosf(0.5f * prz[j], &sz, &cz);
    const float r00x =  cy*cx, r00y =  sy*sx;
    const float r01x = -sy*cx, r01y = -cy*sx;
    const float r10x =  sy*cx, r10y = -cy*sx;
    const float r11x =  cy*cx, r11y = -sy*sx;
    const float u0 = r00x*cz + r00y*sz, u1 = r00y*cz - r00x*sz;
    const float u2 = r01x*cz + r01y*sz, u3 = r01y*cz - r01x*sz;
    const float u4 = r10x*cz - r10y*sz, u5 = r10x*sz + r10y*cz;
    const float u6 = r11x*cz - r11y*sz, u7 = r11x*sz + r11y*cz;
    const float th = 0.5f * 3.14159265358979323846f * tanhf(x[b * NQ + j]);
    float c, s; sincosf(th, &s, &c);
    vv[j * 2 + 0] = make_float2(u0 * c + u2 * s, u1 * c + u3 * s);
    vv[j * 2 + 1] = make_float2(u4 * c + u6 * s, u5 * c + u7 * s);
  }
  __syncthreads();

  // ===== stage B: build 14 diagonal LUTs (per-CTA) =====
  if (tid < 14 * 32) {
    const int k = tid >> 5, o = tid & 31;
    float2 acc = make_float2(1.0f, 0.0f);
    auto muld = [&](int gate, int xb, int which) {
      const float c = sm[OFF_Z + gate * 6 + 2 + which * 2];
      const float s = sm[OFF_Z + gate * 6 + 3 + which * 2];
      acc = cmul(acc, make_float2(c, xb ? s : -s));
    };
    const int G1 = 0, G2 = 14, G3 = 28;
    switch (k) {
      case L0:  for (int j = 0; j < 5; ++j) muld(G1 + j,     (o >> j) & 1, 1); break;
      case L1:  for (int j = 0; j < 5; ++j) muld(G1 + j,     (o >> j) & 1, 0); break;
      case L2a: for (int j = 0; j < 5; ++j) muld(G1 + 5 + j, (o >> j) & 1, 1); break;
      case L2b: for (int j = 0; j < 5; ++j) muld(G1 + 5 + j, (o >> j) & 1, 0); break;
      case L3a: for (int j = 1; j < 5; ++j) muld(G1 + 9 + j, (o >> j) & 1, 1); break;
      case L3b: for (int j = 1; j < 5; ++j) muld(G1 + 9 + j, ((o >> j) ^ (o >> (j - 1))) & 1, 0);
                for (int j = 0; j < 5; ++j) muld(G2 + 9 + j, (o >> j) & 1, 1); break;
      case L3c: for (int j = 0; j < 5; ++j) muld(G2 + 9 + j, (o >> j) & 1, 0); break;
      case L4a: for (int j = 0; j < 5; ++j) muld(G2 + j,     (o >> j) & 1, 1); break;
      case L4b: for (int j = 0; j < 5; ++j) muld(G2 + j,     (o >> j) & 1, 0); break;
      case L5a: for (int j = 0; j < 4; ++j) muld(G2 + 5 + j, (o >> j) & 1, 1); break;
      case L5b: for (int j = 0; j < 4; ++j) muld(G2 + 5 + j, (o >> j) & 1, 0); break;
      case L6:  for (int j = 0; j < 5; ++j) muld(G3 + 9 + j, (o >> j) & 1, 1); break;
      case L7:  for (int j = 0; j < 5; ++j) muld(G3 + j,     (o >> j) & 1, 1); break;
      case L8:  for (int j = 0; j < 4; ++j) muld(G3 + 5 + j, (o >> j) & 1, 1); break;
    }
    lutbase[k * 32 + o] = acc;
    // D1 of layer 3 dropped: diagonal followed only by permutations + |amp|^2.
  }
  __syncthreads();

  const float* zy = sm + OFF_Z;
  const int cb = (g >> 4) & 1;           // qubit-4 value for S=5 windows
  const int cbm = cb ? 31 : 0;
  float vr[32], vi[32];

  // ===== P1: synth + D2(L0) + Ry G1(0-4) + D1(L1) + C1(0-3)  [S=0] =====
  {
    const int t = g;
    // FIX (r13 bug): seed with qubit-6 vector at x6 = t1^t0 (was vv[5*2+...]).
    float2 P = vv[6 * 2 + ((t ^ (t >> 1)) & 1)];
#pragma unroll
    for (int j = 7; j < NQ; ++j)
      P = cmul(P, vv[j * 2 + (((t >> (j - 5)) ^ (t >> (j - 6))) & 1)]);
    const int t0 = t & 1;
    float2 Pv5[2];                                          // x5 = t0 ^ o4
    Pv5[0] = cmul(P, vv[5 * 2 + t0]);
    Pv5[1] = cmul(P, vv[5 * 2 + (t0 ^ 1)]);
    float2 a34[4];                                          // [o3 + 2*o4]
#pragma unroll
    for (int o3 = 0; o3 < 2; ++o3)
#pragma unroll
      for (int o4 = 0; o4 < 2; ++o4)
        a34[o3 + 2 * o4] = cmul(vv[4 * 2 + (o4 ^ o3)], Pv5[o4]);
    float2 w2[8];                                           // [o2 + 2*o3 + 4*o4]
#pragma unroll
    for (int o2 = 0; o2 < 2; ++o2)
#pragma unroll
      for (int o3 = 0; o3 < 2; ++o3)
#pragma unroll
        for (int o4 = 0; o4 < 2; ++o4)
          w2[o2 + 2 * o3 + 4 * o4] = cmul(vv[3 * 2 + (o3 ^ o2)], a34[o3 + 2 * o4]);
    float2 g8[8];                                           // [o0 + 2*o1 + 4*o2]
#pragma unroll
    for (int o0 = 0; o0 < 2; ++o0)
#pragma unroll
      for (int o1 = 0; o1 < 2; ++o1) {
        const float2 h = cmul(vv[0 * 2 + o0], vv[1 * 2 + (o1 ^ o0)]);
#pragma unroll
        for (int o2 = 0; o2 < 2; ++o2)
          g8[o0 + 2 * o1 + 4 * o2] = cmul(h, vv[2 * 2 + (o2 ^ o1)]);
      }
#pragma unroll
    for (int o = 0; o < 32; ++o) {
      const float2 a = cmul(g8[o & 7], w2[(o >> 2) & 7]);
      vr[o] = a.x; vi[o] = a.y;
    }
    applyLUT(vr, vi, lutbase + L0 * 32);
    ryBit5<0>(vr, vi, zy + 0 * 6);
    ryBit5<1>(vr, vi, zy + 1 * 6);
    ryBit5<2>(vr, vi, zy + 2 * 6);
    ryBit5<3>(vr, vi, zy + 3 * 6);
    ryBit5<4>(vr, vi, zy + 4 * 6);
    applyLUT(vr, vi, lutbase + L1 * 32);
    store32<0, true>(st, g, vr, vi, 0);
  }
  __syncwarp();

  // ===== P2: D2(L2a) + Ry G1(5-9) + D1(L2b) + C1(4-8)  [S=5] =====
  {
    load32<5>(st, g, vr, vi);
    applyLUT(vr, vi, lutbase + L2a * 32);
    ryBit5<0>(vr, vi, zy + 5 * 6);
    ryBit5<1>(vr, vi, zy + 6 * 6);
    ryBit5<2>(vr, vi, zy + 7 * 6);
    ryBit5<3>(vr, vi, zy + 8 * 6);
    ryBit5<4>(vr, vi, zy + 9 * 6);
    applyLUT(vr, vi, lutbase + L2b * 32);
    store32<5, true>(st, g, vr, vi, cbm);
  }
  __syncthreads();

  // ===== P3: D2(L3a) + Ry G1(10-13) + [C1(9-12) + D1G1/D2G2 (L3b)] + Ry G2(9-13) + D1(L3c)  [S=9] =====
  {
    load32<9>(st, g, vr, vi);
    applyLUT(vr, vi, lutbase + L3a * 32);
    ryBit5<1>(vr, vi, zy + 10 * 6);
    ryBit5<2>(vr, vi, zy + 11 * 6);
    ryBit5<3>(vr, vi, zy + 12 * 6);
    ryBit5<4>(vr, vi, zy + 13 * 6);
    float wr[32], wi[32];
    relabel5(vr, vi, wr, wi);
    applyLUT(wr, wi, lutbase + L3b * 32);
    ryBit5<0>(wr, wi, zy + (14 + 9) * 6);
    ryBit5<1>(wr, wi, zy + (14 + 10) * 6);
    ryBit5<2>(wr, wi, zy + (14 + 11) * 6);
    ryBit5<3>(wr, wi, zy + (14 + 12) * 6);
    ryBit5<4>(wr, wi, zy + (14 + 13) * 6);
    applyLUT(wr, wi, lutbase + L3c * 32);
    store32<9, false>(st, g, wr, wi, 0);
  }
  __syncthreads();

  // ===== P4: D2(L4a) + Ry G2(0-4) + D1(L4b) + C2(0-3)  [S=0] =====
  {
    load32<0>(st, g, vr, vi);
    applyLUT(vr, vi, lutbase + L4a * 32);
    ryBit5<0>(vr, vi, zy + (14 + 0) * 6);
    ryBit5<1>(vr, vi, zy + (14 + 1) * 6);
    ryBit5<2>(vr, vi, zy + (14 + 2) * 6);
    ryBit5<3>(vr, vi, zy + (14 + 3) * 6);
    ryBit5<4>(vr, vi, zy + (14 + 4) * 6);
    applyLUT(vr, vi, lutbase + L4b * 32);
    store32<0, true>(st, g, vr, vi, 0);
  }
  __syncwarp();

  // ===== P5: D2(L5a) + Ry G2(5-8) + D1(L5b) + C2(4-8)  [S=5] =====
  {
    load32<5>(st, g, vr, vi);
    applyLUT(vr, vi, lutbase + L5a * 32);
    ryBit5<0>(vr, vi, zy + (14 + 5) * 6);
    ryBit5<1>(vr, vi, zy + (14 + 6) * 6);
    ryBit5<2>(vr, vi, zy + (14 + 7) * 6);
    ryBit5<3>(vr, vi, zy + (14 + 8) * 6);
    applyLUT(vr, vi, lutbase + L5b * 32);
    store32<5, true>(st, g, vr, vi, cbm);
  }
  __syncthreads();

  // ===== P6: C2(9-12) + D2(L6) + Ry G3(9-13)  [S=9]  (D1 of layer 3 dropped) =====
  {
    load32<9>(st, g, vr, vi);
    float wr[32], wi[32];
    relabel5(vr, vi, wr, wi);
    applyLUT(wr, wi, lutbase + L6 * 32);
    ryBit5<0>(wr, wi, zy + (28 + 9) * 6);
    ryBit5<1>(wr, wi, zy + (28 + 10) * 6);
    ryBit5<2>(wr, wi, zy + (28 + 11) * 6);
    ryBit5<3>(wr, wi, zy + (28 + 12) * 6);
    ryBit5<4>(wr, wi, zy + (28 + 13) * 6);
    store32<9, false>(st, g, wr, wi, 0);
  }
  __syncthreads();

  // ===== P7: D2(L7) + Ry G3(0-4) + C3(0-3)  [S=0] =====
  {
    load32<0>(st, g, vr, vi);
    applyLUT(vr, vi, lutbase + L7 * 32);
    ryBit5<0>(vr, vi, zy + (28 + 0) * 6);
    ryBit5<1>(vr, vi, zy + (28 + 1) * 6);
    ryBit5<2>(vr, vi, zy + (28 + 2) * 6);
    ryBit5<3>(vr, vi, zy + (28 + 3) * 6);
    ryBit5<4>(vr, vi, zy + (28 + 4) * 6);
    store32<0, true>(st, g, vr, vi, 0);
  }
  __syncwarp();

  // ===== P8: D2(L8) + Ry G3(5-8) + C3(4-8)  [S=5] =====
  {
    load32<5>(st, g, vr, vi);
    applyLUT(vr, vi, lutbase + L8 * 32);
    ryBit5<0>(vr, vi, zy + (28 + 5) * 6);
    ryBit5<1>(vr, vi, zy + (28 + 6) * 6);
    ryBit5<2>(vr, vi, zy + (28 + 7) * 6);
    ryBit5<3>(vr, vi, zy + (28 + 8) * 6);
    store32<5, true>(st, g, vr, vi, cbm);
  }
  __syncthreads();

  // ===== P9: C3(9-12) + MEAS  [S=9] =====
  float acc[NQ];
  {
    load32<9>(st, g, vr, vi);
    float tot = 0.0f, s0 = 0.0f, s1 = 0.0f, s2 = 0.0f, s3 = 0.0f, s4 = 0.0f;
#pragma unroll
    for (int o = 0; o < 32; ++o) {
      const float pr = vr[o] * vr[o] + vi[o] * vi[o];
      const int m = pxm5(o);
      tot += pr;
      if (m & 1)  s0 += pr;
      if (m & 2)  s1 += pr;
      if (m & 4)  s2 += pr;
      if (m & 8)  s3 += pr;
      if (m & 16) s4 += pr;
    }
    acc[9]  = tot - 2.0f * s0;
    acc[10] = tot - 2.0f * s1;
    acc[11] = tot - 2.0f * s2;
    acc[12] = tot - 2.0f * s3;
    acc[13] = tot - 2.0f * s4;
#pragma unroll
    for (int q = 0; q < 9; ++q)
      acc[q] = ((g >> q) & 1) ? -tot : tot;
  }

  // ---- reduction ----
#pragma unroll
  for (int q = 0; q < NQ; ++q)
#pragma unroll
    for (int off = 16; off > 0; off >>= 1)
      acc[q] += __shfl_xor_sync(0xffffffffu, acc[q], off);
  const int warp = tid >> 5;
  __syncthreads();
  if ((tid & 31) == 0) {
#pragma unroll
    for (int q = 0; q < NQ; ++q) sm[OFF_RED + warp * NQ + q] = acc[q];
  }
  __syncthreads();
  if (tid < NQ) {
    float s = 0.0f;
#pragma unroll
    for (int w = 0; w < NWARP; ++w) s += sm[OFF_RED + w * NQ + tid];
    out[b * NQ + tid] = s;
  }
}

} // namespace qc

extern "C" void kernel_launch(void* const* d_in, const int* in_sizes, int n_in,
                              void* d_out, int out_size) {
  const float* x    = (const float*)d_in[0];
  const float* prx  = (const float*)d_in[1];
  const float* pry  = (const float*)d_in[2];
  const float* prz  = (const float*)d_in[3];
  const float* pent = (const float*)d_in[4];
  float* out = (float*)d_out;
  const int batch = in_sizes[0] / qc::NQ;   // 128
  cudaFuncSetAttribute(qc::qc_kernel, cudaFuncAttributeMaxDynamicSharedMemorySize,
                       qc::SMEM_BYTES);
  qc::qc_kernel<<<batch, qc::NT, qc::SMEM_BYTES>>>(x, prx, pry, prz, pent, out);
}

// round 15
// speedup vs baseline: 1.2962x; 1.0308x over previous
#include <cuda_runtime.h>

namespace qc {

constexpr int NQ = 14;
constexpr int NS = 1 << NQ;       // 16384 amplitudes
constexpr int NT = 1024;          // 32 warps; lane pair (lane, lane^16) shares a 32-amp window
constexpr int NC = NQ - 1;
constexpr int NWARP = NT / 32;
constexpr int NGATE = 42;         // layers 1..3 x 14 qubits

// shared layout (float offsets). State float2[NS].
constexpr int OFF_Z   = 2 * NS;                  // 42 gates * 6: cb2 sb2 cg sg ca sa
constexpr int OFF_V   = OFF_Z + NGATE * 6;       // 14 qubits * 2 cplx product vectors
constexpr int OFF_LUT = OFF_V + NQ * 4;          // 14 LUTs * 32 float2
constexpr int OFF_RED = OFF_LUT + 14 * 64;
constexpr int SMEM_FLOATS = OFF_RED + NWARP * NQ;
constexpr int SMEM_BYTES  = SMEM_FLOATS * 4;

enum { L0 = 0, L1, L2a, L2b, L3a, L3b, L3c, L4a, L4b, L5a, L5b, L6, L7, L8 };

__device__ __forceinline__ int swz(int i) { return i ^ ((i >> 5) & 31); }

__device__ __forceinline__ float2 cmul(float2 a, float2 b) {
  return make_float2(a.x * b.x - a.y * b.y, a.x * b.y + a.y * b.x);
}

// 4-bit prefix-xor relabel (in-thread part of the window CNOT chain)
__host__ __device__ constexpr int pxm4(int o) {
  return (o ^ (o << 1) ^ (o << 2) ^ (o << 3)) & 15;
}

// ---- lane-pair window addressing (r11, proven): bits S..S+3 in-thread, bit S+4 = p ----
template<int S>
__device__ __forceinline__ int wbase(int g, int p) {
  return (((g >> S) << (S + 5)) | (g & ((1 << S) - 1))) | (p << (S + 4));
}

template<int S>
__device__ __forceinline__ void load16(const float2* __restrict__ st, int g, int p,
                                       float* vr, float* vi) {
  const int base = wbase<S>(g, p);
#pragma unroll
  for (int o = 0; o < 16; ++o) {
    const float2 v = st[swz(base | (o << S))];
    vr[o] = v.x; vi[o] = v.y;
  }
}

// load with folded bit-4 exchange (swap where parity(o)==1) — pure address math
template<int S>
__device__ __forceinline__ void loadSwap16(const float2* __restrict__ st, int g, int p,
                                           float* vr, float* vi) {
  const int baseA = wbase<S>(g, p);
  const int baseF = baseA ^ (1 << (S + 4));
#pragma unroll
  for (int o = 0; o < 16; ++o) {
    const int base = (__popc(o) & 1) ? baseF : baseA;
    const float2 v = st[swz(base | (o << S))];
    vr[o] = v.x; vi[o] = v.y;
  }
}

template<int S, bool PX>
__device__ __forceinline__ void store16(float2* __restrict__ st, int g, int p,
                                        const float* vr, const float* vi, int cbmask) {
  const int base = wbase<S>(g, p);
#pragma unroll
  for (int o = 0; o < 16; ++o) {
    const int m = (PX ? pxm4(o) : o) ^ cbmask;
    st[swz(base | (m << S))] = make_float2(vr[o], vi[o]);
  }
}

// store with pxm4 relabel + cbmask + folded bit-4 flip (flip = parity(o) ^ cb)
template<int S>
__device__ __forceinline__ void storeSwap16(float2* __restrict__ st, int g, int p,
                                            const float* vr, const float* vi,
                                            int cbmask, int cb) {
  const int baseA = wbase<S>(g, p);
  const int baseF = baseA ^ (1 << (S + 4));
  const int baseEven = cb ? baseF : baseA;
  const int baseOdd  = cb ? baseA : baseF;
#pragma unroll
  for (int o = 0; o < 16; ++o) {
    const int m = pxm4(o) ^ cbmask;
    const int base = (__popc(o) & 1) ? baseOdd : baseEven;
    st[swz(base | (m << S))] = make_float2(vr[o], vi[o]);
  }
}

// in-thread REAL Ry butterfly on local bit J (16 amps): z = {cos, sin}
template<int J>
__device__ __forceinline__ void ryBit4(float* vr, float* vi, const float* __restrict__ z) {
  const float c = z[0], s = z[1];
#pragma unroll
  for (int o = 0; o < 16; ++o) {
    if (o & (1 << J)) continue;
    const int o1 = o | (1 << J);
    const float ar = vr[o], ai = vi[o], br = vr[o1], bi = vi[o1];
    vr[o]  = c*ar - s*br;   vi[o]  = c*ai - s*bi;
    vr[o1] = s*ar + c*br;   vi[o1] = s*ai + c*bi;
  }
}

// cross-lane REAL Ry on window bit 4: out = c*own + (p? +s : -s)*partner
__device__ __forceinline__ void ryCross(float* vr, float* vi, const float* __restrict__ z, int p) {
  const float c = z[0];
  const float sp = p ? z[1] : -z[1];
#pragma unroll
  for (int o = 0; o < 16; ++o) {
    const float qr = __shfl_xor_sync(0xffffffffu, vr[o], 16);
    const float qi = __shfl_xor_sync(0xffffffffu, vi[o], 16);
    vr[o] = c*vr[o] + sp*qr;
    vi[o] = c*vi[o] + sp*qi;
  }
}

// cross-lane Ry MERGED with CNOT-exchange (swap where parity(o)==1):
//  par=0: out = c*own + sp*partner ; par=1: out = c*partner - sp*own
__device__ __forceinline__ void ryCrossX(float* vr, float* vi, const float* __restrict__ z, int p) {
  const float c = z[0];
  const float sp = p ? z[1] : -z[1];
#pragma unroll
  for (int o = 0; o < 16; ++o) {
    const float qr = __shfl_xor_sync(0xffffffffu, vr[o], 16);
    const float qi = __shfl_xor_sync(0xffffffffu, vi[o], 16);
    if (__popc(o) & 1) { vr[o] = c*qr - sp*vr[o]; vi[o] = c*qi - sp*vi[o]; }
    else               { vr[o] = c*vr[o] + sp*qr; vi[o] = c*vi[o] + sp*qi; }
  }
}

// apply 32-entry complex diagonal LUT; effective label L = (p<<4)|o
__device__ __forceinline__ void applyLUT16(float* vr, float* vi,
                                           const float2* __restrict__ lut, int p) {
  const float2* l = lut + (p << 4);
#pragma unroll
  for (int o = 0; o < 16; ++o) {
    const float2 w = l[o];
    const float r = vr[o] * w.x - vi[o] * w.y;
    vi[o] = vr[o] * w.y + vi[o] * w.x;
    vr[o] = r;
  }
}

__device__ __forceinline__ void relabel4(const float* vr, const float* vi,
                                         float* wr, float* wi) {
#pragma unroll
  for (int o = 0; o < 16; ++o) { wr[pxm4(o)] = vr[o]; wi[pxm4(o)] = vi[o]; }
}

__global__ void __launch_bounds__(NT, 1)
qc_kernel(const float* __restrict__ x, const float* __restrict__ prx,
          const float* __restrict__ pry, const float* __restrict__ prz,
          const float* __restrict__ pent, float* __restrict__ out) {
  extern __shared__ float sm[];
  float2* st = reinterpret_cast<float2*>(sm);
  float2* vv = reinterpret_cast<float2*>(sm + OFF_V);
  float2* lutbase = reinterpret_cast<float2*>(sm + OFF_LUT);
  const int tid  = threadIdx.x;
  const int lane = tid & 31;
  const int g    = (tid >> 5) * 16 + (lane & 15);   // window id 0..511
  const int p    = (lane >> 4) & 1;                 // window bit 4
  const int b    = blockIdx.x;

  // ===== stage A: per-gate ZYZ (layers 1..3, ent-RZ merged) + layer-0 vectors (r14, proven) =====
  if (tid < NGATE) {
    const int q = tid % NQ;
    const int idx = tid + NQ;
    float cx, sx, cy, sy, cz, sz;
    sincosf(0.5f * prx[idx], &sx, &cx);
    sincosf(0.5f * pry[idx], &sy, &cy);
    sincosf(0.5f * prz[idx], &sz, &cz);
    const float r00x =  cy*cx, r00y =  sy*sx;
    const float r01x = -sy*cx, r01y = -cy*sx;
    const float r10x =  sy*cx, r10y = -cy*sx;
    float u0 = r00x*cz + r00y*sz, u1 = r00y*cz - r00x*sz;
    float u2 = r01x*cz + r01y*sz, u3 = r01y*cz - r01x*sz;
    float u4 = r10x*cz - r10y*sz, u5 = r10x*sz + r10y*cz;
    if (q >= 1) {
      float c, s; sincosf(0.5f * pent[(tid / NQ) * NC + (q - 1)], &s, &c);
      float a;
      a = u0*c + u1*s;  u1 = u1*c - u0*s;  u0 = a;
      a = u4*c + u5*s;  u5 = u5*c - u4*s;  u4 = a;
      a = u2*c - u3*s;  u3 = u3*c + u2*s;  u2 = a;
    }
    const float cb2 = sqrtf(u0*u0 + u1*u1);
    const float sb2 = sqrtf(u4*u4 + u5*u5);
    const float php = -atan2f(u1, u0);
    const float phm =  atan2f(u5, u4);
    float sg, cg, sa, ca;
    sincosf(0.5f * (php + phm), &sg, &cg);
    sincosf(0.5f * (php - phm), &sa, &ca);
    float* z = sm + OFF_Z + tid * 6;
    z[0] = cb2; z[1] = sb2; z[2] = cg; z[3] = sg; z[4] = ca; z[5] = sa;
  }
  if (tid >= 64 && tid < 64 + NQ) {
    const int j = tid - 64;
    float cx, sx, cy, sy, cz, sz;
    sincosf(0.5f * prx[j], &sx, &cx);
    sincosf(0.5f * pry[j], &sy, &cy);
    sincosf(0.5f * prz[j], &sz, &cz);
    const float r00x =  cy*cx, r00y =  sy*sx;
    const float r01x = -sy*cx, r01y = -cy*sx;
    const float r10x =  sy*cx, r10y = -cy*sx;
    const float r11x =  cy*cx, r11y = -sy*sx;
    const float u0 = r00x*cz + r00y*sz, u1 = r00y*cz - r00x*sz;
    const float u2 = r01x*cz + r01y*sz, u3 = r01y*cz - r01x*sz;
    const float u4 = r10x*cz - r10y*sz, u5 = r10x*sz + r10y*cz;
    const float u6 = r11x*cz - r11y*sz, u7 = r11x*sz + r11y*cz;
    const float th = 0.5f * 3.14159265358979323846f * tanhf(x[b * NQ + j]);
    float c, s; sincosf(th, &s, &c);
    vv[j * 2 + 0] = make_float2(u0 * c + u2 * s, u1 * c + u3 * s);
    vv[j * 2 + 1] = make_float2(u4 * c + u6 * s, u5 * c + u7 * s);
  }
  __syncthreads();

  // ===== stage B: 14 diagonal LUTs (r14, proven; label-space formulas) =====
  if (tid < 14 * 32) {
    const int k = tid >> 5, o = tid & 31;
    float2 acc = make_float2(1.0f, 0.0f);
    auto muld = [&](int gate, int xb, int which) {
      const float c = sm[OFF_Z + gate * 6 + 2 + which * 2];
      const float s = sm[OFF_Z + gate * 6 + 3 + which * 2];
      acc = cmul(acc, make_float2(c, xb ? s : -s));
    };
    const int G1 = 0, G2 = 14, G3 = 28;
    switch (k) {
      case L0:  for (int j = 0; j < 5; ++j) muld(G1 + j,     (o >> j) & 1, 1); break;
      case L1:  for (int j = 0; j < 5; ++j) muld(G1 + j,     (o >> j) & 1, 0); break;
      case L2a: for (int j = 0; j < 5; ++j) muld(G1 + 5 + j, (o >> j) & 1, 1); break;
      case L2b: for (int j = 0; j < 5; ++j) muld(G1 + 5 + j, (o >> j) & 1, 0); break;
      case L3a: for (int j = 1; j < 5; ++j) muld(G1 + 9 + j, (o >> j) & 1, 1); break;
      case L3b: for (int j = 1; j < 5; ++j) muld(G1 + 9 + j, ((o >> j) ^ (o >> (j - 1))) & 1, 0);
                for (int j = 0; j < 5; ++j) muld(G2 + 9 + j, (o >> j) & 1, 1); break;
      case L3c: for (int j = 0; j < 5; ++j) muld(G2 + 9 + j, (o >> j) & 1, 0); break;
      case L4a: for (int j = 0; j < 5; ++j) muld(G2 + j,     (o >> j) & 1, 1); break;
      case L4b: for (int j = 0; j < 5; ++j) muld(G2 + j,     (o >> j) & 1, 0); break;
      case L5a: for (int j = 0; j < 4; ++j) muld(G2 + 5 + j, (o >> j) & 1, 1); break;
      case L5b: for (int j = 0; j < 4; ++j) muld(G2 + 5 + j, (o >> j) & 1, 0); break;
      case L6:  for (int j = 0; j < 5; ++j) muld(G3 + 9 + j, (o >> j) & 1, 1); break;
      case L7:  for (int j = 0; j < 5; ++j) muld(G3 + j,     (o >> j) & 1, 1); break;
      case L8:  for (int j = 0; j < 4; ++j) muld(G3 + 5 + j, (o >> j) & 1, 1); break;
    }
    lutbase[k * 32 + o] = acc;
  }
  __syncthreads();

  const float* zy = sm + OFF_Z;
  const int cb = (g >> 4) & 1;           // qubit-4 value for S=5 windows (warp-uniform)
  const int cbm = cb ? 15 : 0;
  float vr[16], vi[16];

  // ===== P1: synth + D2(L0) + Ry G1(0-4) + D1(L1) + C1(0-3)  [S=0] =====
  {
    // r11 synth (proven): amp(y), y bits 0-3=o, 4=p, 5-13=g
    float2 Pg = vv[5 * 2 + ((g ^ p) & 1)];
#pragma unroll
    for (int j = 6; j < NQ; ++j)
      Pg = cmul(Pg, vv[j * 2 + (((g >> (j - 5)) ^ (g >> (j - 6))) & 1)]);
    float2 t4[2];
    t4[0] = cmul(vv[4 * 2 + p], Pg);
    t4[1] = cmul(vv[4 * 2 + (p ^ 1)], Pg);
    float2 r34[4];
#pragma unroll
    for (int o2 = 0; o2 < 2; ++o2)
#pragma unroll
      for (int o3 = 0; o3 < 2; ++o3)
        r34[o2 + 2 * o3] = cmul(vv[3 * 2 + (o3 ^ o2)], t4[o3]);
    float2 qv[8];
#pragma unroll
    for (int o1 = 0; o1 < 2; ++o1)
#pragma unroll
      for (int o2 = 0; o2 < 2; ++o2)
#pragma unroll
        for (int o3 = 0; o3 < 2; ++o3)
          qv[o1 + 2 * o2 + 4 * o3] = cmul(vv[2 * 2 + (o2 ^ o1)], r34[o2 + 2 * o3]);
    float2 e01[4];
#pragma unroll
    for (int o0 = 0; o0 < 2; ++o0)
#pragma unroll
      for (int o1 = 0; o1 < 2; ++o1)
        e01[o0 + 2 * o1] = cmul(vv[0 * 2 + o0], vv[1 * 2 + (o1 ^ o0)]);
#pragma unroll
    for (int o = 0; o < 16; ++o) {
      const float2 a = cmul(e01[o & 3], qv[(o >> 1) & 7]);
      vr[o] = a.x; vi[o] = a.y;
    }
    applyLUT16(vr, vi, lutbase + L0 * 32, p);
    ryBit4<0>(vr, vi, zy + 0 * 6);
    ryBit4<1>(vr, vi, zy + 1 * 6);
    ryBit4<2>(vr, vi, zy + 2 * 6);
    ryBit4<3>(vr, vi, zy + 3 * 6);
    ryCross(vr, vi, zy + 4 * 6, p);
    applyLUT16(vr, vi, lutbase + L1 * 32, p);
    storeSwap16<0>(st, g, p, vr, vi, 0, 0);   // c0-c2 via pxm4; c3 via lane flip
  }
  __syncthreads();

  // ===== P2: D2(L2a) + Ry G1(5-9) + D1(L2b) + C1(4-8)  [S=5] =====
  {
    load16<5>(st, g, p, vr, vi);
    applyLUT16(vr, vi, lutbase + L2a * 32, p);
    ryBit4<0>(vr, vi, zy + 5 * 6);
    ryBit4<1>(vr, vi, zy + 6 * 6);
    ryBit4<2>(vr, vi, zy + 7 * 6);
    ryBit4<3>(vr, vi, zy + 8 * 6);
    ryCross(vr, vi, zy + 9 * 6, p);
    applyLUT16(vr, vi, lutbase + L2b * 32, p);
    storeSwap16<5>(st, g, p, vr, vi, cbm, cb);  // c4 out + c5-c7 labels + c8 lane flip
  }
  __syncthreads();

  // ===== P3: D2(L3a) + Ry G1(10-13) (+c12 merged) + C1(9-11) + D(L3b) + Ry G2(9-13) + D1(L3c)  [S=9] =====
  {
    load16<9>(st, g, p, vr, vi);
    applyLUT16(vr, vi, lutbase + L3a * 32, p);
    ryBit4<1>(vr, vi, zy + 10 * 6);
    ryBit4<2>(vr, vi, zy + 11 * 6);
    ryBit4<3>(vr, vi, zy + 12 * 6);
    ryCrossX(vr, vi, zy + 13 * 6, p);            // G1(13) + c12 exchange merged
    float wr[16], wi[16];
    relabel4(vr, vi, wr, wi);                    // c9-c11
    applyLUT16(wr, wi, lutbase + L3b * 32, p);
    ryBit4<0>(wr, wi, zy + (14 + 9) * 6);
    ryBit4<1>(wr, wi, zy + (14 + 10) * 6);
    ryBit4<2>(wr, wi, zy + (14 + 11) * 6);
    ryBit4<3>(wr, wi, zy + (14 + 12) * 6);
    ryCross(wr, wi, zy + (14 + 13) * 6, p);
    applyLUT16(wr, wi, lutbase + L3c * 32, p);
    store16<9, false>(st, g, p, wr, wi, 0);
  }
  __syncthreads();

  // ===== P4: D2(L4a) + Ry G2(0-4) + D1(L4b) + C2(0-3)  [S=0] =====
  {
    load16<0>(st, g, p, vr, vi);
    applyLUT16(vr, vi, lutbase + L4a * 32, p);
    ryBit4<0>(vr, vi, zy + (14 + 0) * 6);
    ryBit4<1>(vr, vi, zy + (14 + 1) * 6);
    ryBit4<2>(vr, vi, zy + (14 + 2) * 6);
    ryBit4<3>(vr, vi, zy + (14 + 3) * 6);
    ryCross(vr, vi, zy + (14 + 4) * 6, p);
    applyLUT16(vr, vi, lutbase + L4b * 32, p);
    storeSwap16<0>(st, g, p, vr, vi, 0, 0);
  }
  __syncthreads();

  // ===== P5: D2(L5a) + Ry G2(5-8) + D1(L5b) + C2(4-8)  [S=5] =====
  {
    load16<5>(st, g, p, vr, vi);
    applyLUT16(vr, vi, lutbase + L5a * 32, p);
    ryBit4<0>(vr, vi, zy + (14 + 5) * 6);
    ryBit4<1>(vr, vi, zy + (14 + 6) * 6);
    ryBit4<2>(vr, vi, zy + (14 + 7) * 6);
    ryBit4<3>(vr, vi, zy + (14 + 8) * 6);
    // G2(9) already applied in P3
    applyLUT16(vr, vi, lutbase + L5b * 32, p);
    storeSwap16<5>(st, g, p, vr, vi, cbm, cb);
  }
  __syncthreads();

  // ===== P6: C2(9-12) + D2(L6) + Ry G3(9-13)  [S=9]  (layer-3 D1 dropped) =====
  {
    loadSwap16<9>(st, g, p, vr, vi);             // c12 folded into load lane bit
    float wr[16], wi[16];
    relabel4(vr, vi, wr, wi);                    // c9-c11
    applyLUT16(wr, wi, lutbase + L6 * 32, p);
    ryBit4<0>(wr, wi, zy + (28 + 9) * 6);
    ryBit4<1>(wr, wi, zy + (28 + 10) * 6);
    ryBit4<2>(wr, wi, zy + (28 + 11) * 6);
    ryBit4<3>(wr, wi, zy + (28 + 12) * 6);
    ryCross(wr, wi, zy + (28 + 13) * 6, p);
    store16<9, false>(st, g, p, wr, wi, 0);
  }
  __syncthreads();

  // ===== P7: D2(L7) + Ry G3(0-4) + C3(0-3)  [S=0] =====
  {
    load16<0>(st, g, p, vr, vi);
    applyLUT16(vr, vi, lutbase + L7 * 32, p);
    ryBit4<0>(vr, vi, zy + (28 + 0) * 6);
    ryBit4<1>(vr, vi, zy + (28 + 1) * 6);
    ryBit4<2>(vr, vi, zy + (28 + 2) * 6);
    ryBit4<3>(vr, vi, zy + (28 + 3) * 6);
    ryCross(vr, vi, zy + (28 + 4) * 6, p);
    storeSwap16<0>(st, g, p, vr, vi, 0, 0);
  }
  __syncthreads();

  // ===== P8: D2(L8) + Ry G3(5-8) + C3(4-8)  [S=5] =====
  {
    load16<5>(st, g, p, vr, vi);
    applyLUT16(vr, vi, lutbase + L8 * 32, p);
    ryBit4<0>(vr, vi, zy + (28 + 5) * 6);
    ryBit4<1>(vr, vi, zy + (28 + 6) * 6);
    ryBit4<2>(vr, vi, zy + (28 + 7) * 6);
    ryBit4<3>(vr, vi, zy + (28 + 8) * 6);
    storeSwap16<5>(st, g, p, vr, vi, cbm, cb);
  }
  __syncthreads();

  // ===== P9: C3(9-12) + MEAS  [S=9]  (r11 measurement, proven) =====
  float acc[NQ];
  {
    load16<9>(st, g, p, vr, vi);
    float tot = 0.0f, s0 = 0.0f, s1 = 0.0f, s2 = 0.0f, s3 = 0.0f;
#pragma unroll
    for (int o = 0; o < 16; ++o) {
      const float pr = vr[o] * vr[o] + vi[o] * vi[o];
      const int m = pxm4(o);               // labels after c9-c11
      tot += pr;
      if (m & 1) s0 += pr;
      if (m & 2) s1 += pr;
      if (m & 4) s2 += pr;
      if (m & 8) s3 += pr;
    }
    acc[9]  = tot - 2.0f * s0;
    acc[10] = tot - 2.0f * s1;
    acc[11] = tot - 2.0f * s2;
    acc[12] = tot - 2.0f * s3;
    acc[13] = p ? (2.0f * s3 - tot) : (tot - 2.0f * s3);   // q13 = p ^ parity(o) (c12 folded)
#pragma unroll
    for (int q = 0; q < 9; ++q)
      acc[q] = ((g >> q) & 1) ? -tot : tot;
  }

  // ---- reduction ----
#pragma unroll
  for (int q = 0; q < NQ; ++q)
#pragma unroll
    for (int off = 16; off > 0; off >>= 1)
      acc[q] += __shfl_xor_sync(0xffffffffu, acc[q], off);
  const int warp = tid >> 5;
  __syncthreads();
  if ((tid & 31) == 0) {
#pragma unroll
    for (int q = 0; q < NQ; ++q) sm[OFF_RED + warp * NQ + q] = acc[q];
  }
  __syncthreads();
  if (tid < NQ) {
    float s = 0.0f;
#pragma unroll
    for (int w = 0; w < NWARP; ++w) s += sm[OFF_RED + w * NQ + tid];
    out[b * NQ + tid] = s;
  }
}

} // namespace qc

extern "C" void kernel_launch(void* const* d_in, const int* in_sizes, int n_in,
                              void* d_out, int out_size) {
  const float* x    = (const float*)d_in[0];
  const float* prx  = (const float*)d_in[1];
  const float* pry  = (const float*)d_in[2];
  const float* prz  = (const float*)d_in[3];
  const float* pent = (const float*)d_in[4];
  float* out = (float*)d_out;
  const int batch = in_sizes[0] / qc::NQ;   // 128
  cudaFuncSetAttribute(qc::qc_kernel, cudaFuncAttributeMaxDynamicSharedMemorySize,
                       qc::SMEM_BYTES);
  qc::qc_kernel<<<batch, qc::NT, qc::SMEM_BYTES>>>(x, prx, pry, prz, pent, out);
}

// round 16
// speedup vs baseline: 1.3128x; 1.0128x over previous
#include <cuda_runtime.h>

namespace qc {

constexpr int NQ = 14;
constexpr int NS = 1 << NQ;       // 16384 amplitudes
constexpr int NT = 1024;          // 32 warps; lane pair (lane, lane^16) shares a 32-amp window
constexpr int NC = NQ - 1;
constexpr int NWARP = NT / 32;
constexpr int NGATE = 42;         // layers 1..3 x 14 qubits

// shared layout (float offsets). State float2[NS].
constexpr int OFF_Z   = 2 * NS;                  // 42 gates * 6: cb2 sb2 cg sg ca sa
constexpr int OFF_V   = OFF_Z + NGATE * 6;       // 14 qubits * 2 cplx product vectors
constexpr int OFF_C   = OFF_V + NQ * 4;          // 448 component-LUT float2
constexpr int OFF_M   = OFF_C + 448 * 2;         // 4608 merged-LUT float2
constexpr int OFF_RED = OFF_M + 4608 * 2;
constexpr int SMEM_FLOATS = OFF_RED + NWARP * NQ;
constexpr int SMEM_BYTES  = SMEM_FLOATS * 4;     // ~171 KB

// component LUT float2 offsets (within cbase)
constexpr int C_L1I = 0,   C_L2A = 32,  C_L2BI = 64,  C_L3A = 128, C_L3B = 144;
constexpr int C_L3C = 176, C_L4A = 208, C_L4BI = 240, C_L5A = 272, C_L5BI = 288;
constexpr int C_L6  = 320, C_L7  = 352, C_L8  = 384,  C_L0  = 416;
// merged LUT float2 offsets (within mbase)
constexpr int M_1 = 0, M_2 = 1024, M_4 = 2048, M_5 = 3072, M_6 = 3584;

__device__ __forceinline__ int swz(int i) { return i ^ ((i >> 5) & 31); }

__device__ __forceinline__ float2 cmul(float2 a, float2 b) {
  return make_float2(a.x * b.x - a.y * b.y, a.x * b.y + a.y * b.x);
}

__host__ __device__ constexpr int pxm4(int o) {
  return (o ^ (o << 1) ^ (o << 2) ^ (o << 3)) & 15;
}

// ---- lane-pair window addressing (r11/r15, proven) ----
template<int S>
__device__ __forceinline__ int wbase(int g, int p) {
  return (((g >> S) << (S + 5)) | (g & ((1 << S) - 1))) | (p << (S + 4));
}

template<int S>
__device__ __forceinline__ void load16(const float2* __restrict__ st, int g, int p,
                                       float* vr, float* vi) {
  const int base = wbase<S>(g, p);
#pragma unroll
  for (int o = 0; o < 16; ++o) {
    const float2 v = st[swz(base | (o << S))];
    vr[o] = v.x; vi[o] = v.y;
  }
}

template<int S>
__device__ __forceinline__ void loadSwap16(const float2* __restrict__ st, int g, int p,
                                           float* vr, float* vi) {
  const int baseA = wbase<S>(g, p);
  const int baseF = baseA ^ (1 << (S + 4));
#pragma unroll
  for (int o = 0; o < 16; ++o) {
    const int base = (__popc(o) & 1) ? baseF : baseA;
    const float2 v = st[swz(base | (o << S))];
    vr[o] = v.x; vi[o] = v.y;
  }
}

template<int S, bool PX>
__device__ __forceinline__ void store16(float2* __restrict__ st, int g, int p,
                                        const float* vr, const float* vi, int cbmask) {
  const int base = wbase<S>(g, p);
#pragma unroll
  for (int o = 0; o < 16; ++o) {
    const int m = (PX ? pxm4(o) : o) ^ cbmask;
    st[swz(base | (m << S))] = make_float2(vr[o], vi[o]);
  }
}

template<int S>
__device__ __forceinline__ void storeSwap16(float2* __restrict__ st, int g, int p,
                                            const float* vr, const float* vi,
                                            int cbmask, int cb) {
  const int baseA = wbase<S>(g, p);
  const int baseF = baseA ^ (1 << (S + 4));
  const int baseEven = cb ? baseF : baseA;
  const int baseOdd  = cb ? baseA : baseF;
#pragma unroll
  for (int o = 0; o < 16; ++o) {
    const int m = pxm4(o) ^ cbmask;
    const int base = (__popc(o) & 1) ? baseOdd : baseEven;
    st[swz(base | (m << S))] = make_float2(vr[o], vi[o]);
  }
}

template<int J>
__device__ __forceinline__ void ryBit4(float* vr, float* vi, const float* __restrict__ z) {
  const float c = z[0], s = z[1];
#pragma unroll
  for (int o = 0; o < 16; ++o) {
    if (o & (1 << J)) continue;
    const int o1 = o | (1 << J);
    const float ar = vr[o], ai = vi[o], br = vr[o1], bi = vi[o1];
    vr[o]  = c*ar - s*br;   vi[o]  = c*ai - s*bi;
    vr[o1] = s*ar + c*br;   vi[o1] = s*ai + c*bi;
  }
}

__device__ __forceinline__ void ryCross(float* vr, float* vi, const float* __restrict__ z, int p) {
  const float c = z[0];
  const float sp = p ? z[1] : -z[1];
#pragma unroll
  for (int o = 0; o < 16; ++o) {
    const float qr = __shfl_xor_sync(0xffffffffu, vr[o], 16);
    const float qi = __shfl_xor_sync(0xffffffffu, vi[o], 16);
    vr[o] = c*vr[o] + sp*qr;
    vi[o] = c*vi[o] + sp*qi;
  }
}

__device__ __forceinline__ void ryCrossX(float* vr, float* vi, const float* __restrict__ z, int p) {
  const float c = z[0];
  const float sp = p ? z[1] : -z[1];
#pragma unroll
  for (int o = 0; o < 16; ++o) {
    const float qr = __shfl_xor_sync(0xffffffffu, vr[o], 16);
    const float qi = __shfl_xor_sync(0xffffffffu, vi[o], 16);
    if (__popc(o) & 1) { vr[o] = c*qr - sp*vr[o]; vi[o] = c*qi - sp*vi[o]; }
    else               { vr[o] = c*vr[o] + sp*qr; vi[o] = c*vi[o] + sp*qi; }
  }
}

// 32-entry LUT apply, label L = (p<<4)|o (r15, proven)
__device__ __forceinline__ void applyLUT16(float* vr, float* vi,
                                           const float2* __restrict__ lut, int p) {
  const float2* l = lut + (p << 4);
#pragma unroll
  for (int o = 0; o < 16; ++o) {
    const float2 w = l[o];
    const float r = vr[o] * w.x - vi[o] * w.y;
    vi[o] = vr[o] * w.y + vi[o] * w.x;
    vr[o] = r;
  }
}

// merged LUT apply: entry index = base + (o<<5)
__device__ __forceinline__ void applyM(float* vr, float* vi,
                                       const float2* __restrict__ lut, int base) {
#pragma unroll
  for (int o = 0; o < 16; ++o) {
    const float2 w = lut[base + (o << 5)];
    const float r = vr[o] * w.x - vi[o] * w.y;
    vi[o] = vr[o] * w.y + vi[o] * w.x;
    vr[o] = r;
  }
}

__device__ __forceinline__ void relabel4(const float* vr, const float* vi,
                                         float* wr, float* wi) {
#pragma unroll
  for (int o = 0; o < 16; ++o) { wr[pxm4(o)] = vr[o]; wi[pxm4(o)] = vi[o]; }
}

__global__ void __launch_bounds__(NT, 1)
qc_kernel(const float* __restrict__ x, const float* __restrict__ prx,
          const float* __restrict__ pry, const float* __restrict__ prz,
          const float* __restrict__ pent, float* __restrict__ out) {
  extern __shared__ float sm[];
  float2* st = reinterpret_cast<float2*>(sm);
  float2* vv = reinterpret_cast<float2*>(sm + OFF_V);
  float2* cbase = reinterpret_cast<float2*>(sm + OFF_C);
  float2* mbase = reinterpret_cast<float2*>(sm + OFF_M);
  const int tid  = threadIdx.x;
  const int lane = tid & 31;
  const int g    = (tid >> 5) * 16 + (lane & 15);   // window id 0..511
  const int p    = (lane >> 4) & 1;                 // window bit 4
  const int b    = blockIdx.x;

  // ===== stage A: per-gate ZYZ (layers 1..3, ent-RZ merged) + layer-0 vectors (r15, proven) =====
  if (tid < NGATE) {
    const int q = tid % NQ;
    const int idx = tid + NQ;
    float cx, sx, cy, sy, cz, sz;
    sincosf(0.5f * prx[idx], &sx, &cx);
    sincosf(0.5f * pry[idx], &sy, &cy);
    sincosf(0.5f * prz[idx], &sz, &cz);
    const float r00x =  cy*cx, r00y =  sy*sx;
    const float r01x = -sy*cx, r01y = -cy*sx;
    const float r10x =  sy*cx, r10y = -cy*sx;
    float u0 = r00x*cz + r00y*sz, u1 = r00y*cz - r00x*sz;
    float u2 = r01x*cz + r01y*sz, u3 = r01y*cz - r01x*sz;
    float u4 = r10x*cz - r10y*sz, u5 = r10x*sz + r10y*cz;
    if (q >= 1) {
      float c, s; sincosf(0.5f * pent[(tid / NQ) * NC + (q - 1)], &s, &c);
      float a;
      a = u0*c + u1*s;  u1 = u1*c - u0*s;  u0 = a;
      a = u4*c + u5*s;  u5 = u5*c - u4*s;  u4 = a;
      a = u2*c - u3*s;  u3 = u3*c + u2*s;  u2 = a;
    }
    const float cb2 = sqrtf(u0*u0 + u1*u1);
    const float sb2 = sqrtf(u4*u4 + u5*u5);
    const float php = -atan2f(u1, u0);
    const float phm =  atan2f(u5, u4);
    float sg, cg, sa, ca;
    sincosf(0.5f * (php + phm), &sg, &cg);
    sincosf(0.5f * (php - phm), &sa, &ca);
    float* z = sm + OFF_Z + tid * 6;
    z[0] = cb2; z[1] = sb2; z[2] = cg; z[3] = sg; z[4] = ca; z[5] = sa;
  }
  if (tid >= 64 && tid < 64 + NQ) {
    const int j = tid - 64;
    float cx, sx, cy, sy, cz, sz;
    sincosf(0.5f * prx[j], &sx, &cx);
    sincosf(0.5f * pry[j], &sy, &cy);
    sincosf(0.5f * prz[j], &sz, &cz);
    const float r00x =  cy*cx, r00y =  sy*sx;
    const float r01x = -sy*cx, r01y = -cy*sx;
    const float r10x =  sy*cx, r10y = -cy*sx;
    const float r11x =  cy*cx, r11y = -sy*sx;
    const float u0 = r00x*cz + r00y*sz, u1 = r00y*cz - r00x*sz;
    const float u2 = r01x*cz + r01y*sz, u3 = r01y*cz - r01x*sz;
    const float u4 = r10x*cz - r10y*sz, u5 = r10x*sz + r10y*cz;
    const float u6 = r11x*cz - r11y*sz, u7 = r11x*sz + r11y*cz;
    const float th = 0.5f * 3.14159265358979323846f * tanhf(x[b * NQ + j]);
    float c, s; sincosf(th, &s, &c);
    vv[j * 2 + 0] = make_float2(u0 * c + u2 * s, u1 * c + u3 * s);
    vv[j * 2 + 1] = make_float2(u4 * c + u6 * s, u5 * c + u7 * s);
  }
  __syncthreads();

  // ===== stage B1: component LUTs =====
  // Chain semantics are CUMULATIVE prefix-xor: Y_j = X_0^..^X_j, so the
  // deferred-D1 inverse is pairwise: X_j = Y_j ^ Y_{j-1}.
  if (tid < 448) {
    const int t = tid;
    float2 acc = make_float2(1.0f, 0.0f);
    auto muld = [&](int gate, int xb, int which) {
      const float c = sm[OFF_Z + gate * 6 + 2 + which * 2];
      const float s = sm[OFF_Z + gate * 6 + 3 + which * 2];
      acc = cmul(acc, make_float2(c, xb ? s : -s));
    };
    const int G1 = 0, G2 = 14, G3 = 28;
    if (t < 32) {                       // cL1inv[y]: D1 G1(0-4), deferred past c0-c3
      const int y = t;
      muld(G1 + 0, y & 1, 0);
      for (int j = 1; j < 5; ++j) muld(G1 + j, ((y >> j) ^ (y >> (j - 1))) & 1, 0);
    } else if (t < 64) {                // cL2a[z]: D2 G1(5-9)
      const int z = t - 32;
      for (int j = 0; j < 5; ++j) muld(G1 + 5 + j, (z >> j) & 1, 1);
    } else if (t < 128) {               // cL2binv[u]: D1 G1(5-9), u=(Y4..Y8,Y9), X(5+j)=u_{j+1}^u_j
      const int u = t - 64;
      for (int j = 0; j < 5; ++j) muld(G1 + 5 + j, ((u >> (j + 1)) ^ (u >> j)) & 1, 0);
    } else if (t < 144) {               // cL3a[v]: D2 G1(10-13)
      const int v = t - 128;
      for (int j = 0; j < 4; ++j) muld(G1 + 10 + j, (v >> j) & 1, 1);
    } else if (t < 176) {               // L3b[o]: r14 verbatim (mid-pass, kept)
      const int o = t - 144;
      for (int j = 1; j < 5; ++j) muld(G1 + 9 + j, ((o >> j) ^ (o >> (j - 1))) & 1, 0);
      for (int j = 0; j < 5; ++j) muld(G2 + 9 + j, (o >> j) & 1, 1);
    } else if (t < 208) {               // cL3c[w]: D1 G2(9-13) (no inversion needed)
      const int w = t - 176;
      for (int j = 0; j < 5; ++j) muld(G2 + 9 + j, (w >> j) & 1, 0);
    } else if (t < 240) {               // cL4a[z]: D2 G2(0-4)
      const int z = t - 208;
      for (int j = 0; j < 5; ++j) muld(G2 + j, (z >> j) & 1, 1);
    } else if (t < 272) {               // cL4binv[y]: D1 G2(0-4), deferred past c0-c3
      const int y = t - 240;
      muld(G2 + 0, y & 1, 0);
      for (int j = 1; j < 5; ++j) muld(G2 + j, ((y >> j) ^ (y >> (j - 1))) & 1, 0);
    } else if (t < 288) {               // cL5a[z]: D2 G2(5-8)
      const int z = t - 272;
      for (int j = 0; j < 4; ++j) muld(G2 + 5 + j, (z >> j) & 1, 1);
    } else if (t < 320) {               // cL5binv[u]: D1 G2(5-8), u=(Y4..Y8)
      const int u = t - 288;
      for (int j = 0; j < 4; ++j) muld(G2 + 5 + j, ((u >> (j + 1)) ^ (u >> j)) & 1, 0);
    } else if (t < 352) {               // cL6[w]: D2 G3(9-13)
      const int w = t - 320;
      for (int j = 0; j < 5; ++j) muld(G3 + 9 + j, (w >> j) & 1, 1);
    } else if (t < 384) {               // L7[z]: D2 G3(0-4)
      const int z = t - 352;
      for (int j = 0; j < 5; ++j) muld(G3 + j, (z >> j) & 1, 1);
    } else if (t < 416) {               // L8[z]: D2 G3(5-8)
      const int z = t - 384;
      for (int j = 0; j < 4; ++j) muld(G3 + 5 + j, (z >> j) & 1, 1);
    } else {                            // L0[z]: D2 G1(0-4)
      const int z = t - 416;
      for (int j = 0; j < 5; ++j) muld(G1 + j, (z >> j) & 1, 1);
    }
    cbase[t] = acc;
  }
  __syncthreads();

  // ===== stage B2: merged LUTs (1 cmul per entry) =====
  {
    const int i = tid;
    // M1[q0-4(thread Y) | q5-9(label)<<5]
    mbase[M_1 + i] = cmul(cbase[C_L1I + (i & 31)], cbase[C_L2A + (i >> 5)]);
    // M2[(Y4..Y8) | o<<5 | p<<9]: u=(i&31)|(o0<<5), v=(o>>1)|(p<<3)
    mbase[M_2 + i] = cmul(cbase[C_L2BI + ((i & 31) | (((i >> 5) & 1) << 5))],
                          cbase[C_L3A + ((i >> 6) & 15)]);
    // M4[q9-13(thread) | q0-4(label)<<5]
    mbase[M_4 + i] = cmul(cbase[C_L3C + (i & 31)], cbase[C_L4A + ((i >> 5) & 31)]);
    // M5[q0-4(thread Y) | q5-8(label)<<5]  (512 entries)
    if (i < 512)
      mbase[M_5 + i] = cmul(cbase[C_L4BI + (i & 31)], cbase[C_L5A + ((i >> 5) & 15)]);
    // M6[(Y4..Y8) | postchain q9-13(label)<<5]
    mbase[M_6 + i] = cmul(cbase[C_L5BI + (i & 31)], cbase[C_L6 + ((i >> 5) & 31)]);
  }
  __syncthreads();

  const float* zy = sm + OFF_Z;
  const int cb = (g >> 4) & 1;           // qubit-4 value for S=5 windows (warp-uniform)
  const int cbm = cb ? 15 : 0;
  const int baseLo = (g & 31) | (p << 9);          // P2 merged index base
  const int baseHi = ((g >> 4) & 31) | (p << 9);   // P3/P4/P6 merged index base
  float vr[16], vi[16];

  // ===== P1: synth + D2(L0) + Ry G1(0-4) + C1(0-3)  [S=0]  (D1 deferred to P2) =====
  {
    float2 Pg = vv[5 * 2 + ((g ^ p) & 1)];
#pragma unroll
    for (int j = 6; j < NQ; ++j)
      Pg = cmul(Pg, vv[j * 2 + (((g >> (j - 5)) ^ (g >> (j - 6))) & 1)]);
    float2 t4[2];
    t4[0] = cmul(vv[4 * 2 + p], Pg);
    t4[1] = cmul(vv[4 * 2 + (p ^ 1)], Pg);
    float2 r34[4];
#pragma unroll
    for (int o2 = 0; o2 < 2; ++o2)
#pragma unroll
      for (int o3 = 0; o3 < 2; ++o3)
        r34[o2 + 2 * o3] = cmul(vv[3 * 2 + (o3 ^ o2)], t4[o3]);
    float2 qv[8];
#pragma unroll
    for (int o1 = 0; o1 < 2; ++o1)
#pragma unroll
      for (int o2 = 0; o2 < 2; ++o2)
#pragma unroll
        for (int o3 = 0; o3 < 2; ++o3)
          qv[o1 + 2 * o2 + 4 * o3] = cmul(vv[2 * 2 + (o2 ^ o1)], r34[o2 + 2 * o3]);
    float2 e01[4];
#pragma unroll
    for (int o0 = 0; o0 < 2; ++o0)
#pragma unroll
      for (int o1 = 0; o1 < 2; ++o1)
        e01[o0 + 2 * o1] = cmul(vv[0 * 2 + o0], vv[1 * 2 + (o1 ^ o0)]);
#pragma unroll
    for (int o = 0; o < 16; ++o) {
      const float2 a = cmul(e01[o & 3], qv[(o >> 1) & 7]);
      vr[o] = a.x; vi[o] = a.y;
    }
    applyLUT16(vr, vi, cbase + C_L0, p);
    ryBit4<0>(vr, vi, zy + 0 * 6);
    ryBit4<1>(vr, vi, zy + 1 * 6);
    ryBit4<2>(vr, vi, zy + 2 * 6);
    ryBit4<3>(vr, vi, zy + 3 * 6);
    ryCross(vr, vi, zy + 4 * 6, p);
    storeSwap16<0>(st, g, p, vr, vi, 0, 0);   // c0-c2 via pxm4; c3 via lane flip
  }
  __syncthreads();

  // ===== P2: M1(D1G1(0-4)xD2G1(5-9)) + Ry G1(5-9) + C1(4-8)  [S=5] =====
  {
    load16<5>(st, g, p, vr, vi);
    applyM(vr, vi, mbase + M_1, baseLo);
    ryBit4<0>(vr, vi, zy + 5 * 6);
    ryBit4<1>(vr, vi, zy + 6 * 6);
    ryBit4<2>(vr, vi, zy + 7 * 6);
    ryBit4<3>(vr, vi, zy + 8 * 6);
    ryCross(vr, vi, zy + 9 * 6, p);
    storeSwap16<5>(st, g, p, vr, vi, cbm, cb);  // c4 (ctrl outside) + c5-c7 + c8 lane flip
  }
  __syncthreads();

  // ===== P3: M2(D1G1(5-9)xD2G1(10-13)) + Ry G1(10-13)(+c12) + C1(9-11) + L3b + Ry G2(9-13)  [S=9] =====
  {
    load16<9>(st, g, p, vr, vi);
    applyM(vr, vi, mbase + M_2, baseHi);
    ryBit4<1>(vr, vi, zy + 10 * 6);
    ryBit4<2>(vr, vi, zy + 11 * 6);
    ryBit4<3>(vr, vi, zy + 12 * 6);
    ryCrossX(vr, vi, zy + 13 * 6, p);            // G1(13) + c12 exchange merged
    float wr[16], wi[16];
    relabel4(vr, vi, wr, wi);                    // c9-c11
    applyLUT16(wr, wi, cbase + C_L3B, p);
    ryBit4<0>(wr, wi, zy + (14 + 9) * 6);
    ryBit4<1>(wr, wi, zy + (14 + 10) * 6);
    ryBit4<2>(wr, wi, zy + (14 + 11) * 6);
    ryBit4<3>(wr, wi, zy + (14 + 12) * 6);
    ryCross(wr, wi, zy + (14 + 13) * 6, p);
    store16<9, false>(st, g, p, wr, wi, 0);      // D1G2(9-13) deferred to P4
  }
  __syncthreads();

  // ===== P4: M4(D1G2(9-13)xD2G2(0-4)) + Ry G2(0-4) + C2(0-3)  [S=0] =====
  {
    load16<0>(st, g, p, vr, vi);
    applyM(vr, vi, mbase + M_4, baseHi);
    ryBit4<0>(vr, vi, zy + (14 + 0) * 6);
    ryBit4<1>(vr, vi, zy + (14 + 1) * 6);
    ryBit4<2>(vr, vi, zy + (14 + 2) * 6);
    ryBit4<3>(vr, vi, zy + (14 + 3) * 6);
    ryCross(vr, vi, zy + (14 + 4) * 6, p);
    storeSwap16<0>(st, g, p, vr, vi, 0, 0);      // D1G2(0-4) deferred to P5
  }
  __syncthreads();

  // ===== P5: M5(D1G2(0-4)xD2G2(5-8)) + Ry G2(5-8) + C2(4-8)  [S=5] =====
  {
    load16<5>(st, g, p, vr, vi);
    applyM(vr, vi, mbase + M_5, g & 31);         // p-independent
    ryBit4<0>(vr, vi, zy + (14 + 5) * 6);
    ryBit4<1>(vr, vi, zy + (14 + 6) * 6);
    ryBit4<2>(vr, vi, zy + (14 + 7) * 6);
    ryBit4<3>(vr, vi, zy + (14 + 8) * 6);
    storeSwap16<5>(st, g, p, vr, vi, cbm, cb);   // D1G2(5-8) deferred to P6
  }
  __syncthreads();

  // ===== P6: C2(9-12) + M6(D1G2(5-8)xD2G3(9-13)) + Ry G3(9-13)  [S=9] =====
  {
    loadSwap16<9>(st, g, p, vr, vi);             // c12 folded into load lane bit
    float wr[16], wi[16];
    relabel4(vr, vi, wr, wi);                    // c9-c11
    applyM(wr, wi, mbase + M_6, baseHi);
    ryBit4<0>(wr, wi, zy + (28 + 9) * 6);
    ryBit4<1>(wr, wi, zy + (28 + 10) * 6);
    ryBit4<2>(wr, wi, zy + (28 + 11) * 6);
    ryBit4<3>(wr, wi, zy + (28 + 12) * 6);
    ryCross(wr, wi, zy + (28 + 13) * 6, p);
    store16<9, false>(st, g, p, wr, wi, 0);      // layer-3 D1 dropped
  }
  __syncthreads();

  // ===== P7: L7 + Ry G3(0-4) + C3(0-3)  [S=0] =====
  {
    load16<0>(st, g, p, vr, vi);
    applyLUT16(vr, vi, cbase + C_L7, p);
    ryBit4<0>(vr, vi, zy + (28 + 0) * 6);
    ryBit4<1>(vr, vi, zy + (28 + 1) * 6);
    ryBit4<2>(vr, vi, zy + (28 + 2) * 6);
    ryBit4<3>(vr, vi, zy + (28 + 3) * 6);
    ryCross(vr, vi, zy + (28 + 4) * 6, p);
    storeSwap16<0>(st, g, p, vr, vi, 0, 0);
  }
  __syncthreads();

  // ===== P8: L8 + Ry G3(5-8) + C3(4-8)  [S=5] =====
  {
    load16<5>(st, g, p, vr, vi);
    applyLUT16(vr, vi, cbase + C_L8, p);
    ryBit4<0>(vr, vi, zy + (28 + 5) * 6);
    ryBit4<1>(vr, vi, zy + (28 + 6) * 6);
    ryBit4<2>(vr, vi, zy + (28 + 7) * 6);
    ryBit4<3>(vr, vi, zy + (28 + 8) * 6);
    storeSwap16<5>(st, g, p, vr, vi, cbm, cb);
  }
  __syncthreads();

  // ===== P9: C3(9-12) + MEAS  [S=9]  (r15, proven) =====
  float acc[NQ];
  {
    load16<9>(st, g, p, vr, vi);
    float tot = 0.0f, s0 = 0.0f, s1 = 0.0f, s2 = 0.0f, s3 = 0.0f;
#pragma unroll
    for (int o = 0; o < 16; ++o) {
      const float pr = vr[o] * vr[o] + vi[o] * vi[o];
      const int m = pxm4(o);
      tot += pr;
      if (m & 1) s0 += pr;
      if (m & 2) s1 += pr;
      if (m & 4) s2 += pr;
      if (m & 8) s3 += pr;
    }
    acc[9]  = tot - 2.0f * s0;
    acc[10] = tot - 2.0f * s1;
    acc[11] = tot - 2.0f * s2;
    acc[12] = tot - 2.0f * s3;
    acc[13] = p ? (2.0f * s3 - tot) : (tot - 2.0f * s3);
#pragma unroll
    for (int q = 0; q < 9; ++q)
      acc[q] = ((g >> q) & 1) ? -tot : tot;
  }

  // ---- reduction ----
#pragma unroll
  for (int q = 0; q < NQ; ++q)
#pragma unroll
    for (int off = 16; off > 0; off >>= 1)
      acc[q] += __shfl_xor_sync(0xffffffffu, acc[q], off);
  const int warp = tid >> 5;
  __syncthreads();
  if ((tid & 31) == 0) {
#pragma unroll
    for (int q = 0; q < NQ; ++q) sm[OFF_RED + warp * NQ + q] = acc[q];
  }
  __syncthreads();
  if (tid < NQ) {
    float s = 0.0f;
#pragma unroll
    for (int w = 0; w < NWARP; ++w) s += sm[OFF_RED + w * NQ + tid];
    out[b * NQ + tid] = s;
  }
}

} // namespace qc

extern "C" void kernel_launch(void* const* d_in, const int* in_sizes, int n_in,
                              void* d_out, int out_size) {
  const float* x    = (const float*)d_in[0];
  const float* prx  = (const float*)d_in[1];
  const float* pry  = (const float*)d_in[2];
  const float* prz  = (const float*)d_in[3];
  const float* pent = (const float*)d_in[4];
  float* out = (float*)d_out;
  const int batch = in_sizes[0] / qc::NQ;   // 128
  cudaFuncSetAttribute(qc::qc_kernel, cudaFuncAttributeMaxDynamicSharedMemorySize,
                       qc::SMEM_BYTES);
  qc::qc_kernel<<<batch, qc::NT, qc::SMEM_BYTES>>>(x, prx, pry, prz, pent, out);
}

// round 17
// speedup vs baseline: 1.3655x; 1.0401x over previous
#include <cuda_runtime.h>

namespace qc {

constexpr int NQ = 14;
constexpr int NS = 1 << NQ;       // 16384 amplitudes
constexpr int NT = 1024;          // 32 warps; lane pair (lane, lane^16) shares a 32-amp window
constexpr int NC = NQ - 1;
constexpr int NWARP = NT / 32;
constexpr int NGATE = 42;         // layers 1..3 x 14 qubits

// shared layout (float offsets). State float2[NS].
constexpr int OFF_Z   = 2 * NS;                  // 42 gates * 6: cb2 sb2 cg sg ca sa
constexpr int OFF_V   = OFF_Z + NGATE * 6;       // 14 qubits * 2 cplx product vectors
constexpr int OFF_C   = OFF_V + NQ * 4;          // 448 component-LUT float2
constexpr int OFF_M   = OFF_C + 448 * 2;         // 4608 merged-LUT float2
constexpr int OFF_RED = OFF_M + 4608 * 2;
constexpr int SMEM_FLOATS = OFF_RED + NWARP * NQ;
constexpr int SMEM_BYTES  = SMEM_FLOATS * 4;     // ~171 KB

// component LUT float2 offsets (within cbase)
constexpr int C_L1I = 0,   C_L2A = 32,  C_L2BI = 64,  C_L3A = 128, C_L3B = 144;
constexpr int C_L3C = 176, C_L4A = 208, C_L4BI = 240, C_L5A = 272, C_L5BI = 288;
constexpr int C_L6  = 320, C_L7  = 352, C_L8  = 384,  C_L0  = 416;
// merged LUT float2 offsets (within mbase)
constexpr int M_1 = 0, M_2 = 1024, M_4 = 2048, M_5 = 3072, M_6 = 3584;

__device__ __forceinline__ int swz(int i) { return i ^ ((i >> 5) & 31); }

__device__ __forceinline__ float2 cmul(float2 a, float2 b) {
  return make_float2(a.x * b.x - a.y * b.y, a.x * b.y + a.y * b.x);
}

__host__ __device__ constexpr int pxm4(int o) {
  return (o ^ (o << 1) ^ (o << 2) ^ (o << 3)) & 15;
}

// ---- lane-pair window addressing (r11/r15, proven) ----
template<int S>
__device__ __forceinline__ int wbase(int g, int p) {
  return (((g >> S) << (S + 5)) | (g & ((1 << S) - 1))) | (p << (S + 4));
}

template<int S>
__device__ __forceinline__ void load16(const float2* __restrict__ st, int g, int p,
                                       float* vr, float* vi) {
  const int base = wbase<S>(g, p);
#pragma unroll
  for (int o = 0; o < 16; ++o) {
    const float2 v = st[swz(base | (o << S))];
    vr[o] = v.x; vi[o] = v.y;
  }
}

template<int S>
__device__ __forceinline__ void loadSwap16(const float2* __restrict__ st, int g, int p,
                                           float* vr, float* vi) {
  const int baseA = wbase<S>(g, p);
  const int baseF = baseA ^ (1 << (S + 4));
#pragma unroll
  for (int o = 0; o < 16; ++o) {
    const int base = (__popc(o) & 1) ? baseF : baseA;
    const float2 v = st[swz(base | (o << S))];
    vr[o] = v.x; vi[o] = v.y;
  }
}

template<int S, bool PX>
__device__ __forceinline__ void store16(float2* __restrict__ st, int g, int p,
                                        const float* vr, const float* vi, int cbmask) {
  const int base = wbase<S>(g, p);
#pragma unroll
  for (int o = 0; o < 16; ++o) {
    const int m = (PX ? pxm4(o) : o) ^ cbmask;
    st[swz(base | (m << S))] = make_float2(vr[o], vi[o]);
  }
}

template<int S>
__device__ __forceinline__ void storeSwap16(float2* __restrict__ st, int g, int p,
                                            const float* vr, const float* vi,
                                            int cbmask, int cb) {
  const int baseA = wbase<S>(g, p);
  const int baseF = baseA ^ (1 << (S + 4));
  const int baseEven = cb ? baseF : baseA;
  const int baseOdd  = cb ? baseA : baseF;
#pragma unroll
  for (int o = 0; o < 16; ++o) {
    const int m = pxm4(o) ^ cbmask;
    const int base = (__popc(o) & 1) ? baseOdd : baseEven;
    st[swz(base | (m << S))] = make_float2(vr[o], vi[o]);
  }
}

template<int J>
__device__ __forceinline__ void ryBit4(float* vr, float* vi, const float* __restrict__ z) {
  const float c = z[0], s = z[1];
#pragma unroll
  for (int o = 0; o < 16; ++o) {
    if (o & (1 << J)) continue;
    const int o1 = o | (1 << J);
    const float ar = vr[o], ai = vi[o], br = vr[o1], bi = vi[o1];
    vr[o]  = c*ar - s*br;   vi[o]  = c*ai - s*bi;
    vr[o1] = s*ar + c*br;   vi[o1] = s*ai + c*bi;
  }
}

__device__ __forceinline__ void ryCross(float* vr, float* vi, const float* __restrict__ z, int p) {
  const float c = z[0];
  const float sp = p ? z[1] : -z[1];
#pragma unroll
  for (int o = 0; o < 16; ++o) {
    const float qr = __shfl_xor_sync(0xffffffffu, vr[o], 16);
    const float qi = __shfl_xor_sync(0xffffffffu, vi[o], 16);
    vr[o] = c*vr[o] + sp*qr;
    vi[o] = c*vi[o] + sp*qi;
  }
}

__device__ __forceinline__ void ryCrossX(float* vr, float* vi, const float* __restrict__ z, int p) {
  const float c = z[0];
  const float sp = p ? z[1] : -z[1];
#pragma unroll
  for (int o = 0; o < 16; ++o) {
    const float qr = __shfl_xor_sync(0xffffffffu, vr[o], 16);
    const float qi = __shfl_xor_sync(0xffffffffu, vi[o], 16);
    if (__popc(o) & 1) { vr[o] = c*qr - sp*vr[o]; vi[o] = c*qi - sp*vi[o]; }
    else               { vr[o] = c*vr[o] + sp*qr; vi[o] = c*vi[o] + sp*qi; }
  }
}

__device__ __forceinline__ void applyLUT16(float* vr, float* vi,
                                           const float2* __restrict__ lut, int p) {
  const float2* l = lut + (p << 4);
#pragma unroll
  for (int o = 0; o < 16; ++o) {
    const float2 w = l[o];
    const float r = vr[o] * w.x - vi[o] * w.y;
    vi[o] = vr[o] * w.y + vi[o] * w.x;
    vr[o] = r;
  }
}

__device__ __forceinline__ void applyM(float* vr, float* vi,
                                       const float2* __restrict__ lut, int base) {
#pragma unroll
  for (int o = 0; o < 16; ++o) {
    const float2 w = lut[base + (o << 5)];
    const float r = vr[o] * w.x - vi[o] * w.y;
    vi[o] = vr[o] * w.y + vi[o] * w.x;
    vr[o] = r;
  }
}

// multiply all 16 amps by one complex scalar
__device__ __forceinline__ void applySc(float* vr, float* vi, float2 sc) {
#pragma unroll
  for (int o = 0; o < 16; ++o) {
    const float r = vr[o] * sc.x - vi[o] * sc.y;
    vi[o] = vr[o] * sc.y + vi[o] * sc.x;
    vr[o] = r;
  }
}

__device__ __forceinline__ void relabel4(const float* vr, const float* vi,
                                         float* wr, float* wi) {
#pragma unroll
  for (int o = 0; o < 16; ++o) { wr[pxm4(o)] = vr[o]; wi[pxm4(o)] = vi[o]; }
}

__global__ void __launch_bounds__(NT, 1)
qc_kernel(const float* __restrict__ x, const float* __restrict__ prx,
          const float* __restrict__ pry, const float* __restrict__ prz,
          const float* __restrict__ pent, float* __restrict__ out) {
  extern __shared__ float sm[];
  float2* st = reinterpret_cast<float2*>(sm);
  float2* vv = reinterpret_cast<float2*>(sm + OFF_V);
  float2* cbase = reinterpret_cast<float2*>(sm + OFF_C);
  float2* mbase = reinterpret_cast<float2*>(sm + OFF_M);
  const int tid  = threadIdx.x;
  const int lane = tid & 31;
  const int g    = (tid >> 5) * 16 + (lane & 15);   // window id 0..511
  const int p    = (lane >> 4) & 1;                 // window bit 4
  const int b    = blockIdx.x;

  // ===== stage A: per-gate ZYZ (layers 1..3, ent-RZ merged) + layer-0 vectors =====
  if (tid < NGATE) {
    const int q = tid % NQ;
    const int idx = tid + NQ;
    float cx, sx, cy, sy, cz, sz;
    sincosf(0.5f * prx[idx], &sx, &cx);
    sincosf(0.5f * pry[idx], &sy, &cy);
    sincosf(0.5f * prz[idx], &sz, &cz);
    const float r00x =  cy*cx, r00y =  sy*sx;
    const float r01x = -sy*cx, r01y = -cy*sx;
    const float r10x =  sy*cx, r10y = -cy*sx;
    float u0 = r00x*cz + r00y*sz, u1 = r00y*cz - r00x*sz;
    float u2 = r01x*cz + r01y*sz, u3 = r01y*cz - r01x*sz;
    float u4 = r10x*cz - r10y*sz, u5 = r10x*sz + r10y*cz;
    if (q >= 1) {
      float c, s; sincosf(0.5f * pent[(tid / NQ) * NC + (q - 1)], &s, &c);
      float a;
      a = u0*c + u1*s;  u1 = u1*c - u0*s;  u0 = a;
      a = u4*c + u5*s;  u5 = u5*c - u4*s;  u4 = a;
      a = u2*c - u3*s;  u3 = u3*c + u2*s;  u2 = a;
    }
    const float cb2 = sqrtf(u0*u0 + u1*u1);
    const float sb2 = sqrtf(u4*u4 + u5*u5);
    const float php = -atan2f(u1, u0);
    const float phm =  atan2f(u5, u4);
    float sg, cg, sa, ca;
    sincosf(0.5f * (php + phm), &sg, &cg);
    sincosf(0.5f * (php - phm), &sa, &ca);
    float* z = sm + OFF_Z + tid * 6;
    z[0] = cb2; z[1] = sb2; z[2] = cg; z[3] = sg; z[4] = ca; z[5] = sa;
  }
  if (tid >= 64 && tid < 64 + NQ) {
    const int j = tid - 64;
    float cx, sx, cy, sy, cz, sz;
    sincosf(0.5f * prx[j], &sx, &cx);
    sincosf(0.5f * pry[j], &sy, &cy);
    sincosf(0.5f * prz[j], &sz, &cz);
    const float r00x =  cy*cx, r00y =  sy*sx;
    const float r01x = -sy*cx, r01y = -cy*sx;
    const float r10x =  sy*cx, r10y = -cy*sx;
    const float r11x =  cy*cx, r11y = -sy*sx;
    const float u0 = r00x*cz + r00y*sz, u1 = r00y*cz - r00x*sz;
    const float u2 = r01x*cz + r01y*sz, u3 = r01y*cz - r01x*sz;
    const float u4 = r10x*cz - r10y*sz, u5 = r10x*sz + r10y*cz;
    const float u6 = r11x*cz - r11y*sz, u7 = r11x*sz + r11y*cz;
    const float th = 0.5f * 3.14159265358979323846f * tanhf(x[b * NQ + j]);
    float c, s; sincosf(th, &s, &c);
    vv[j * 2 + 0] = make_float2(u0 * c + u2 * s, u1 * c + u3 * s);
    vv[j * 2 + 1] = make_float2(u4 * c + u6 * s, u5 * c + u7 * s);
  }
  __syncthreads();

  // ===== stage B1: component LUTs (r16, proven) =====
  if (tid < 448) {
    const int t = tid;
    float2 acc = make_float2(1.0f, 0.0f);
    auto muld = [&](int gate, int xb, int which) {
      const float c = sm[OFF_Z + gate * 6 + 2 + which * 2];
      const float s = sm[OFF_Z + gate * 6 + 3 + which * 2];
      acc = cmul(acc, make_float2(c, xb ? s : -s));
    };
    const int G1 = 0, G2 = 14, G3 = 28;
    if (t < 32) {
      const int y = t;
      muld(G1 + 0, y & 1, 0);
      for (int j = 1; j < 5; ++j) muld(G1 + j, ((y >> j) ^ (y >> (j - 1))) & 1, 0);
    } else if (t < 64) {
      const int z = t - 32;
      for (int j = 0; j < 5; ++j) muld(G1 + 5 + j, (z >> j) & 1, 1);
    } else if (t < 128) {
      const int u = t - 64;
      for (int j = 0; j < 5; ++j) muld(G1 + 5 + j, ((u >> (j + 1)) ^ (u >> j)) & 1, 0);
    } else if (t < 144) {
      const int v = t - 128;
      for (int j = 0; j < 4; ++j) muld(G1 + 10 + j, (v >> j) & 1, 1);
    } else if (t < 176) {
      const int o = t - 144;
      for (int j = 1; j < 5; ++j) muld(G1 + 9 + j, ((o >> j) ^ (o >> (j - 1))) & 1, 0);
      for (int j = 0; j < 5; ++j) muld(G2 + 9 + j, (o >> j) & 1, 1);
    } else if (t < 208) {
      const int w = t - 176;
      for (int j = 0; j < 5; ++j) muld(G2 + 9 + j, (w >> j) & 1, 0);
    } else if (t < 240) {
      const int z = t - 208;
      for (int j = 0; j < 5; ++j) muld(G2 + j, (z >> j) & 1, 1);
    } else if (t < 272) {
      const int y = t - 240;
      muld(G2 + 0, y & 1, 0);
      for (int j = 1; j < 5; ++j) muld(G2 + j, ((y >> j) ^ (y >> (j - 1))) & 1, 0);
    } else if (t < 288) {
      const int z = t - 272;
      for (int j = 0; j < 4; ++j) muld(G2 + 5 + j, (z >> j) & 1, 1);
    } else if (t < 320) {
      const int u = t - 288;
      for (int j = 0; j < 4; ++j) muld(G2 + 5 + j, ((u >> (j + 1)) ^ (u >> j)) & 1, 0);
    } else if (t < 352) {
      const int w = t - 320;
      for (int j = 0; j < 5; ++j) muld(G3 + 9 + j, (w >> j) & 1, 1);
    } else if (t < 384) {
      const int z = t - 352;
      for (int j = 0; j < 5; ++j) muld(G3 + j, (z >> j) & 1, 1);
    } else if (t < 416) {
      const int z = t - 384;
      for (int j = 0; j < 4; ++j) muld(G3 + 5 + j, (z >> j) & 1, 1);
    } else {
      const int z = t - 416;
      for (int j = 0; j < 5; ++j) muld(G1 + j, (z >> j) & 1, 1);
    }
    cbase[t] = acc;
  }
  __syncthreads();

  // ===== stage B2: merged LUTs (r16, proven) =====
  {
    const int i = tid;
    mbase[M_1 + i] = cmul(cbase[C_L1I + (i & 31)], cbase[C_L2A + (i >> 5)]);
    mbase[M_2 + i] = cmul(cbase[C_L2BI + ((i & 31) | (((i >> 5) & 1) << 5))],
                          cbase[C_L3A + ((i >> 6) & 15)]);
    mbase[M_4 + i] = cmul(cbase[C_L3C + (i & 31)], cbase[C_L4A + ((i >> 5) & 31)]);
    if (i < 512)
      mbase[M_5 + i] = cmul(cbase[C_L4BI + (i & 31)], cbase[C_L5A + ((i >> 5) & 15)]);
    mbase[M_6 + i] = cmul(cbase[C_L5BI + (i & 31)], cbase[C_L6 + ((i >> 5) & 31)]);
  }
  __syncthreads();

  const float* zy = sm + OFF_Z;
  const int cb = (g >> 4) & 1;
  const int cbm = cb ? 15 : 0;
  const int baseLo = (g & 31) | (p << 9);
  const int baseHi = ((g >> 4) & 31) | (p << 9);
  float vr[16], vi[16];

  // ===== P1: synth + D2(L0) + Ry G1(0-4) + C1(0-3)  [S=0] =====
  {
    float2 Pg = vv[5 * 2 + ((g ^ p) & 1)];
#pragma unroll
    for (int j = 6; j < NQ; ++j)
      Pg = cmul(Pg, vv[j * 2 + (((g >> (j - 5)) ^ (g >> (j - 6))) & 1)]);
    float2 t4[2];
    t4[0] = cmul(vv[4 * 2 + p], Pg);
    t4[1] = cmul(vv[4 * 2 + (p ^ 1)], Pg);
    float2 r34[4];
#pragma unroll
    for (int o2 = 0; o2 < 2; ++o2)
#pragma unroll
      for (int o3 = 0; o3 < 2; ++o3)
        r34[o2 + 2 * o3] = cmul(vv[3 * 2 + (o3 ^ o2)], t4[o3]);
    float2 qv[8];
#pragma unroll
    for (int o1 = 0; o1 < 2; ++o1)
#pragma unroll
      for (int o2 = 0; o2 < 2; ++o2)
#pragma unroll
        for (int o3 = 0; o3 < 2; ++o3)
          qv[o1 + 2 * o2 + 4 * o3] = cmul(vv[2 * 2 + (o2 ^ o1)], r34[o2 + 2 * o3]);
    float2 e01[4];
#pragma unroll
    for (int o0 = 0; o0 < 2; ++o0)
#pragma unroll
      for (int o1 = 0; o1 < 2; ++o1)
        e01[o0 + 2 * o1] = cmul(vv[0 * 2 + o0], vv[1 * 2 + (o1 ^ o0)]);
#pragma unroll
    for (int o = 0; o < 16; ++o) {
      const float2 a = cmul(e01[o & 3], qv[(o >> 1) & 7]);
      vr[o] = a.x; vi[o] = a.y;
    }
    applyLUT16(vr, vi, cbase + C_L0, p);
    ryBit4<0>(vr, vi, zy + 0 * 6);
    ryBit4<1>(vr, vi, zy + 1 * 6);
    ryBit4<2>(vr, vi, zy + 2 * 6);
    ryBit4<3>(vr, vi, zy + 3 * 6);
    ryCross(vr, vi, zy + 4 * 6, p);
    storeSwap16<0>(st, g, p, vr, vi, 0, 0);
  }
  __syncthreads();

  // ===== P2: M1 + Ry G1(5-9) + C1(4-8)  [S=5] =====
  {
    load16<5>(st, g, p, vr, vi);
    applyM(vr, vi, mbase + M_1, baseLo);
    ryBit4<0>(vr, vi, zy + 5 * 6);
    ryBit4<1>(vr, vi, zy + 6 * 6);
    ryBit4<2>(vr, vi, zy + 7 * 6);
    ryBit4<3>(vr, vi, zy + 8 * 6);
    ryCross(vr, vi, zy + 9 * 6, p);
    storeSwap16<5>(st, g, p, vr, vi, cbm, cb);
  }
  __syncthreads();

  // ===== P3: M2 + Ry G1(10-13)(+c12) + C1(9-11) + L3b + Ry G2(9-13)  [S=9] =====
  {
    load16<9>(st, g, p, vr, vi);
    applyM(vr, vi, mbase + M_2, baseHi);
    ryBit4<1>(vr, vi, zy + 10 * 6);
    ryBit4<2>(vr, vi, zy + 11 * 6);
    ryBit4<3>(vr, vi, zy + 12 * 6);
    ryCrossX(vr, vi, zy + 13 * 6, p);
    float wr[16], wi[16];
    relabel4(vr, vi, wr, wi);
    applyLUT16(wr, wi, cbase + C_L3B, p);
    ryBit4<0>(wr, wi, zy + (14 + 9) * 6);
    ryBit4<1>(wr, wi, zy + (14 + 10) * 6);
    ryBit4<2>(wr, wi, zy + (14 + 11) * 6);
    ryBit4<3>(wr, wi, zy + (14 + 12) * 6);
    ryCross(wr, wi, zy + (14 + 13) * 6, p);
    store16<9, false>(st, g, p, wr, wi, 0);
  }
  __syncthreads();

  // ===== P4: M4 + Ry G2(0-4) + C2(0-3)  [S=0] =====
  {
    load16<0>(st, g, p, vr, vi);
    applyM(vr, vi, mbase + M_4, baseHi);
    ryBit4<0>(vr, vi, zy + (14 + 0) * 6);
    ryBit4<1>(vr, vi, zy + (14 + 1) * 6);
    ryBit4<2>(vr, vi, zy + (14 + 2) * 6);
    ryBit4<3>(vr, vi, zy + (14 + 3) * 6);
    ryCross(vr, vi, zy + (14 + 4) * 6, p);
    storeSwap16<0>(st, g, p, vr, vi, 0, 0);
  }
  __syncthreads();

  // ===== P5: M5 + Ry G2(5-8) + C2(4-8)  [S=5] =====
  {
    load16<5>(st, g, p, vr, vi);
    applyM(vr, vi, mbase + M_5, g & 31);
    ryBit4<0>(vr, vi, zy + (14 + 5) * 6);
    ryBit4<1>(vr, vi, zy + (14 + 6) * 6);
    ryBit4<2>(vr, vi, zy + (14 + 7) * 6);
    ryBit4<3>(vr, vi, zy + (14 + 8) * 6);
    storeSwap16<5>(st, g, p, vr, vi, cbm, cb);
  }
  __syncthreads();

  // ===== P6: C2(9-12) + M6 + scalar(L7*L8) + Ry G3(9-13)  [S=9] =====
  // D2 G3(0-4) and D2 G3(5-8) depend only on qubits 0-8 = g (thread-fixed here)
  // and commute with everything up to their Ry's at P7/P8 -> applied as one scalar.
  {
    loadSwap16<9>(st, g, p, vr, vi);
    float wr[16], wi[16];
    relabel4(vr, vi, wr, wi);
    applyM(wr, wi, mbase + M_6, baseHi);
    const float2 sc = cmul(cbase[C_L7 + (g & 31)], cbase[C_L8 + ((g >> 5) & 15)]);
    applySc(wr, wi, sc);
    ryBit4<0>(wr, wi, zy + (28 + 9) * 6);
    ryBit4<1>(wr, wi, zy + (28 + 10) * 6);
    ryBit4<2>(wr, wi, zy + (28 + 11) * 6);
    ryBit4<3>(wr, wi, zy + (28 + 12) * 6);
    ryCross(wr, wi, zy + (28 + 13) * 6, p);
    store16<9, false>(st, g, p, wr, wi, 0);
  }
  __syncthreads();

  // ===== P7: Ry G3(0-4) + C3(0-3)  [S=0]  (D2 already applied at P6) =====
  {
    load16<0>(st, g, p, vr, vi);
    ryBit4<0>(vr, vi, zy + (28 + 0) * 6);
    ryBit4<1>(vr, vi, zy + (28 + 1) * 6);
    ryBit4<2>(vr, vi, zy + (28 + 2) * 6);
    ryBit4<3>(vr, vi, zy + (28 + 3) * 6);
    ryCross(vr, vi, zy + (28 + 4) * 6, p);
    storeSwap16<0>(st, g, p, vr, vi, 0, 0);   // c0-c2 labels + c3 lane flip -> bits 0-4 = Y0..Y4
  }
  __syncthreads();

  // ===== P8: Ry G3(5-8) + in-register MEAS (c4-c12 folded into bit algebra)  [S=5] =====
  float acc[NQ];
  {
    load16<5>(st, g, p, vr, vi);
    ryBit4<0>(vr, vi, zy + (28 + 5) * 6);
    ryBit4<1>(vr, vi, zy + (28 + 6) * 6);
    ryBit4<2>(vr, vi, zy + (28 + 7) * 6);
    ryBit4<3>(vr, vi, zy + (28 + 8) * 6);
    // index bits here: 0-4 = Y0..Y4 (=g&31), 5-8 = X5..X8 (=o), 9 = X9 (=p),
    // 10-13 = X10..X13 (=(g>>5)&15). Chain: Y_j = X_j ^ Y_{j-1}.
    float tot = 0.0f, sp0 = 0.0f, sp1 = 0.0f, sp2 = 0.0f, sp3 = 0.0f;
#pragma unroll
    for (int o = 0; o < 16; ++o) {
      const float pr = vr[o] * vr[o] + vi[o] * vi[o];
      tot += pr;
      if (o & 1)                          sp0 += pr;   // X5
      if ((o ^ (o >> 1)) & 1)             sp1 += pr;   // X5^X6
      if ((o ^ (o >> 1) ^ (o >> 2)) & 1)  sp2 += pr;   // X5^X6^X7
      if (__popc(o) & 1)                  sp3 += pr;   // X5^..^X8
    }
    const int sy4 = (g >> 4) & 1;        // Y4 (control of c4)
    float m5 = tot - 2.0f * sp0;
    float m6 = tot - 2.0f * sp1;
    float m7 = tot - 2.0f * sp2;
    float m8 = tot - 2.0f * sp3;
    if (sy4) { m5 = -m5; m6 = -m6; m7 = -m7; m8 = -m8; }
    float a9 = p ? -m8 : m8;             // Y9 = X9 ^ Y8, X9 = p
    acc[5] = m5; acc[6] = m6; acc[7] = m7; acc[8] = m8; acc[9] = a9;
    const int hx = g >> 5;               // X10..X13
    acc[10] = (hx & 1) ? -a9 : a9;                                   // Y10 = X10^Y9
    acc[11] = ((hx ^ (hx >> 1)) & 1) ? -a9 : a9;                     // X10^X11
    acc[12] = ((hx ^ (hx >> 1) ^ (hx >> 2)) & 1) ? -a9 : a9;
    acc[13] = ((hx ^ (hx >> 1) ^ (hx >> 2) ^ (hx >> 3)) & 1) ? -a9 : a9;
#pragma unroll
    for (int q = 0; q < 5; ++q)
      acc[q] = ((g >> q) & 1) ? -tot : tot;   // bits 0-4 already = Y
  }

  // ---- reduction ----
#pragma unroll
  for (int q = 0; q < NQ; ++q)
#pragma unroll
    for (int off = 16; off > 0; off >>= 1)
      acc[q] += __shfl_xor_sync(0xffffffffu, acc[q], off);
  const int warp = tid >> 5;
  if ((tid & 31) == 0) {
#pragma unroll
    for (int q = 0; q < NQ; ++q) sm[OFF_RED + warp * NQ + q] = acc[q];
  }
  __syncthreads();
  if (tid < NQ) {
    float s = 0.0f;
#pragma unroll
    for (int w = 0; w < NWARP; ++w) s += sm[OFF_RED + w * NQ + tid];
    out[b * NQ + tid] = s;
  }
}

} // namespace qc

extern "C" void kernel_launch(void* const* d_in, const int* in_sizes, int n_in,
                              void* d_out, int out_size) {
  const float* x    = (const float*)d_in[0];
  const float* prx  = (const float*)d_in[1];
  const float* pry  = (const float*)d_in[2];
  const float* prz  = (const float*)d_in[3];
  const float* pent = (const float*)d_in[4];
  float* out = (float*)d_out;
  const int batch = in_sizes[0] / qc::NQ;   // 128
  cudaFuncSetAttribute(qc::qc_kernel, cudaFuncAttributeMaxDynamicSharedMemorySize,
                       qc::SMEM_BYTES);
  qc::qc_kernel<<<batch, qc::NT, qc::SMEM_BYTES>>>(x, prx, pry, prz, pent, out);
}